// round 6
// baseline (speedup 1.0000x reference)
#include <cuda_runtime.h>
#include <cuda_bf16.h>
#include <math.h>
#include <stdint.h>

#define NB   2
#define NT   1024
#define ND   2048
#define NH   16
#define NDK  128
#define NTOK (NB*NT)      /* 2048 tokens */
#define NC   (NH*NDK)     /* 2048 channels */
#define KS   (3*ND)       /* 6144: split-precision K (hi|lo|hi) */
#define WSTRIDE ((size_t)NC*KS)

// ------------------------------------------------------------------
// Scratch (device globals; no runtime allocation allowed)
// ------------------------------------------------------------------
__device__ __nv_bfloat16 g_xs[(size_t)NTOK*KS];   // split activations
__device__ __nv_bfloat16 g_ws[6*WSTRIDE];         // 6 split weights (q,k,v,a,g,o) contiguous
__device__ float g_q0[NTOK*NC];
__device__ float g_k0[NTOK*NC];
__device__ float g_v0[NTOK*NC];
__device__ float g_qc[NTOK*NC];
__device__ float g_kc[NTOK*NC];
__device__ float g_vc[NTOK*NC];
__device__ float g_a [NTOK*NC];
__device__ float g_gt[NTOK*NC];
__device__ float g_o8[(size_t)NTOK*NC*8];         // 8 partial recurrence outputs / channel
__device__ float g_bt[NTOK*NH];

// ==================================================================
// Helpers
// ==================================================================
__device__ __forceinline__ uint32_t smem_u32(const void* p) {
    uint32_t r;
    asm("{ .reg .u64 t; cvta.to.shared.u64 t, %1; cvt.u32.u64 %0, t; }"
        : "=r"(r) : "l"(p));
    return r;
}
__device__ __forceinline__ void cp16(uint32_t dst, const void* src) {
    asm volatile("cp.async.cg.shared.global [%0], [%1], 16;\n" :: "r"(dst), "l"(src));
}
__device__ __forceinline__ void cp_commit() {
    asm volatile("cp.async.commit_group;\n" ::: "memory");
}
__device__ __forceinline__ void cp_wait1() {
    asm volatile("cp.async.wait_group 1;\n" ::: "memory");
}
__device__ __forceinline__ void cp_wait0() {
    asm volatile("cp.async.wait_group 0;\n" ::: "memory");
}
__device__ __forceinline__ void ldsm4(uint32_t& r0, uint32_t& r1, uint32_t& r2,
                                      uint32_t& r3, uint32_t addr) {
    asm volatile("ldmatrix.sync.aligned.m8n8.x4.shared.b16 {%0,%1,%2,%3}, [%4];"
                 : "=r"(r0), "=r"(r1), "=r"(r2), "=r"(r3) : "r"(addr));
}
__device__ __forceinline__ void mma16816(float* d, const uint32_t* a,
                                         uint32_t b0, uint32_t b1) {
    asm volatile(
        "mma.sync.aligned.m16n8k16.row.col.f32.bf16.bf16.f32 "
        "{%0,%1,%2,%3}, {%4,%5,%6,%7}, {%8,%9}, {%0,%1,%2,%3};"
        : "+f"(d[0]), "+f"(d[1]), "+f"(d[2]), "+f"(d[3])
        : "r"(a[0]), "r"(a[1]), "r"(a[2]), "r"(a[3]), "r"(b0), "r"(b1));
}
__device__ __forceinline__ float fsig(float z) {
    return 1.f / (1.f + __expf(-z));
}

// ==================================================================
// Tensor-core GEMM (HMMA): one kernel serves
//   - fused 5-projection GEMM: grid.x = 80 (N = 10240 rows of g_ws)
//   - Wo GEMM: grid.x = 16 (seg always 0 -> plain store to Cq)
// 128x128 tile, BK = 64, 3-stage cp.async pipeline (96 KB smem), 8 warps.
// ==================================================================
#define BK      64
#define KITERS  (KS/BK)      /* 96 */
#define STG_B   32768        /* bytes per stage: A 16KB + B 16KB */
#define STAGES  3
#define TG_SMEM (STAGES*STG_B)

__global__ void __launch_bounds__(256, 2)
tgemm(const __nv_bfloat16* __restrict__ A, const __nv_bfloat16* __restrict__ Bw,
      const float* __restrict__ bias_a,
      float* __restrict__ Cq, float* __restrict__ Ck, float* __restrict__ Cv,
      float* __restrict__ Ca, float* __restrict__ Cg)
{
    extern __shared__ __align__(1024) char smem[];
    const uint32_t sb = smem_u32(smem);

    const int tid  = threadIdx.x;
    const int lane = tid & 31;
    const int wid  = tid >> 5;
    const int wm   = wid & 3;
    const int wn   = wid >> 2;
    const int m0   = blockIdx.y * 128;
    const int n0g  = blockIdx.x * 128;
    const int seg  = blockIdx.x >> 4;
    const int col0 = (blockIdx.x & 15) * 128;

    const int r0 = tid >> 3;
    const int c0 = tid & 7;
    const uint32_t stOff = (uint32_t)(((c0 ^ (r0 & 7)) << 4));

    const __nv_bfloat16* gA = A  + (size_t)(m0  + r0) * KS + c0 * 8;
    const __nv_bfloat16* gB = Bw + (size_t)(n0g + r0) * KS + c0 * 8;

    const int la = lane & 15, ha = lane >> 4;
    const int arow = wm * 32 + la;
    const uint32_t aswz = arow & 7;
    const int brow = wn * 64 + (lane & 7) + ((lane >> 4) & 1) * 8;
    const uint32_t bswz = brow & 7;
    const uint32_t bsel = (lane >> 3) & 1;

    uint32_t aoff[4], boff[4];
#pragma unroll
    for (int kh = 0; kh < 4; kh++) {
        aoff[kh] = arow * 128 + (((uint32_t)((2 * kh + ha) ^ aswz)) << 4);
        boff[kh] = 16384 + brow * 128 + (((uint32_t)((2 * kh + bsel) ^ bswz)) << 4);
    }

    float acc[2][8][4];
#pragma unroll
    for (int mi = 0; mi < 2; mi++)
#pragma unroll
        for (int ni = 0; ni < 8; ni++)
#pragma unroll
            for (int e = 0; e < 4; e++) acc[mi][ni][e] = 0.f;

#pragma unroll
    for (int s = 0; s < STAGES - 1; s++) {
        const uint32_t base = sb + s * STG_B;
        const int kc = s * BK;
#pragma unroll
        for (int r = 0; r < 4; r++) {
            const uint32_t so = (r0 + 32 * r) * 128 + stOff;
            cp16(base + so,         gA + (size_t)(32 * r) * KS + kc);
            cp16(base + 16384 + so, gB + (size_t)(32 * r) * KS + kc);
        }
        cp_commit();
    }

    int stage = 0;
    for (int it = 0; it < KITERS; it++) {
        if (it < KITERS - 1) cp_wait1(); else cp_wait0();
        __syncthreads();

        if (it + 2 < KITERS) {
            const int ps = (stage + 2 >= STAGES) ? stage + 2 - STAGES : stage + 2;
            const uint32_t base = sb + ps * STG_B;
            const int kc = (it + 2) * BK;
#pragma unroll
            for (int r = 0; r < 4; r++) {
                const uint32_t so = (r0 + 32 * r) * 128 + stOff;
                cp16(base + so,         gA + (size_t)(32 * r) * KS + kc);
                cp16(base + 16384 + so, gB + (size_t)(32 * r) * KS + kc);
            }
        }
        cp_commit();

        const uint32_t base = sb + stage * STG_B;
        stage = (stage + 1 >= STAGES) ? 0 : stage + 1;

#pragma unroll
        for (int kh = 0; kh < 4; kh++) {
            uint32_t av[2][4];
            ldsm4(av[0][0], av[0][1], av[0][2], av[0][3], base + aoff[kh]);
            ldsm4(av[1][0], av[1][1], av[1][2], av[1][3], base + aoff[kh] + 2048);

            uint32_t bv[4][4];
#pragma unroll
            for (int p = 0; p < 4; p++)
                ldsm4(bv[p][0], bv[p][1], bv[p][2], bv[p][3],
                      base + boff[kh] + p * 2048);

#pragma unroll
            for (int mi = 0; mi < 2; mi++)
#pragma unroll
                for (int ni = 0; ni < 8; ni++) {
                    const int p = ni >> 1;
                    const int h = (ni & 1) * 2;
                    mma16816(acc[mi][ni], av[mi], bv[p][h], bv[p][h + 1]);
                }
        }
    }

    float* C = (seg == 0) ? Cq : (seg == 1) ? Ck : (seg == 2) ? Cv
             : (seg == 3) ? Ca : Cg;
    const int et = (seg == 3) ? 1 : (seg == 4) ? 2 : 0;

    const int g  = lane >> 2;
    const int tg = lane & 3;
#pragma unroll
    for (int mi = 0; mi < 2; mi++) {
        const int row = m0 + wm * 32 + mi * 16 + g;
#pragma unroll
        for (int ni = 0; ni < 8; ni++) {
            const int col = col0 + wn * 64 + ni * 8 + tg * 2;
            float v0 = acc[mi][ni][0], v1 = acc[mi][ni][1];
            float v2 = acc[mi][ni][2], v3 = acc[mi][ni][3];
            if (et == 1) {
                const float b0 = bias_a[col], b1 = bias_a[col + 1];
                v0 = fsig(v0 + b0); v1 = fsig(v1 + b1);
                v2 = fsig(v2 + b0); v3 = fsig(v3 + b1);
            } else if (et == 2) {
                v0 = fsig(v0); v1 = fsig(v1); v2 = fsig(v2); v3 = fsig(v3);
            }
            *(float2*)(C + (size_t)row * NC + col)       = make_float2(v0, v1);
            *(float2*)(C + (size_t)(row + 8) * NC + col) = make_float2(v2, v3);
        }
    }
}

// ------------------------------------------------------------------
// Split fp32 -> bf16 hi/lo, K-concatenated (float4 vectorized).
// ------------------------------------------------------------------
__device__ __forceinline__ void split_body(const float* __restrict__ in,
                                           __nv_bfloat16* __restrict__ out,
                                           int mode, int i)
{
    const int r  = i >> 9;
    const int k4 = (i << 2) & 2047;
    const float4 a = ((const float4*)in)[i];

    __nv_bfloat162 h01 = __floats2bfloat162_rn(a.x, a.y);
    __nv_bfloat162 h23 = __floats2bfloat162_rn(a.z, a.w);
    const float lx = a.x - __bfloat162float(__low2bfloat16(h01));
    const float ly = a.y - __bfloat162float(__high2bfloat16(h01));
    const float lz = a.z - __bfloat162float(__low2bfloat16(h23));
    const float lw = a.w - __bfloat162float(__high2bfloat16(h23));
    __nv_bfloat162 l01 = __floats2bfloat162_rn(lx, ly);
    __nv_bfloat162 l23 = __floats2bfloat162_rn(lz, lw);

    uint2 hp, lp;
    hp.x = *(const uint32_t*)&h01; hp.y = *(const uint32_t*)&h23;
    lp.x = *(const uint32_t*)&l01; lp.y = *(const uint32_t*)&l23;

    __nv_bfloat16* base = out + (size_t)r * KS + k4;
    *(uint2*)(base) = hp;
    if (mode == 0) { *(uint2*)(base + 2048) = lp; *(uint2*)(base + 4096) = hp; }
    else           { *(uint2*)(base + 2048) = hp; *(uint2*)(base + 4096) = lp; }
}

__global__ void __launch_bounds__(256)
split_all(const float* __restrict__ x,  const float* __restrict__ Wq,
          const float* __restrict__ Wk, const float* __restrict__ Wv,
          const float* __restrict__ Wa, const float* __restrict__ Wg,
          const float* __restrict__ Wo,
          __nv_bfloat16* __restrict__ xs, __nv_bfloat16* __restrict__ ws)
{
    const int i = blockIdx.x * 256 + threadIdx.x;
    if (i >= (NTOK * ND) / 4) return;
    const int which = blockIdx.y;
    if (which == 0)      split_body(x,  xs, 0, i);
    else if (which == 1) split_body(Wq, ws + 0 * WSTRIDE, 1, i);
    else if (which == 2) split_body(Wk, ws + 1 * WSTRIDE, 1, i);
    else if (which == 3) split_body(Wv, ws + 2 * WSTRIDE, 1, i);
    else if (which == 4) split_body(Wa, ws + 3 * WSTRIDE, 1, i);
    else if (which == 5) split_body(Wg, ws + 4 * WSTRIDE, 1, i);
    else                 split_body(Wo, ws + 5 * WSTRIDE, 1, i);
}

// ------------------------------------------------------------------
// beta = sigmoid(x @ Wb^T + bb)
// ------------------------------------------------------------------
__global__ void __launch_bounds__(256)
beta_k(const float* __restrict__ x, const float* __restrict__ Wb,
       const float* __restrict__ bb, float* __restrict__ out)
{
    __shared__ float xs[ND];
    const int row = blockIdx.x;
    for (int i = threadIdx.x; i < ND; i += 256) xs[i] = x[(size_t)row * ND + i];
    __syncthreads();
    const int w = threadIdx.x >> 5, lane = threadIdx.x & 31;
    for (int h = w; h < NH; h += 8) {
        const float* wr = Wb + (size_t)h * ND;
        float s = 0.f;
        for (int i = lane; i < ND; i += 32) s = fmaf(xs[i], wr[i], s);
#pragma unroll
        for (int o = 16; o > 0; o >>= 1) s += __shfl_xor_sync(0xffffffffu, s, o);
        if (lane == 0) out[(size_t)row * NH + h] = fsig(s + bb[h]);
    }
}

// ------------------------------------------------------------------
// Fused causal depthwise conv (K=4) + bias + silu + scale, float4, q/k/v
// ------------------------------------------------------------------
__global__ void __launch_bounds__(256)
conv3(const float* __restrict__ q0, const float* __restrict__ k0,
      const float* __restrict__ v0,
      const float* __restrict__ wq, const float* __restrict__ wk,
      const float* __restrict__ wv,
      const float* __restrict__ bq, const float* __restrict__ bk,
      const float* __restrict__ bv,
      float* __restrict__ qc, float* __restrict__ kc, float* __restrict__ vc)
{
    const int i = blockIdx.x * 256 + threadIdx.x;
    if (i >= (NTOK * NC) / 4) return;

    const float* in; const float* w; const float* bias; float* out; float scale;
    if (blockIdx.y == 0)      { in = q0; w = wq; bias = bq; out = qc; scale = 1.f; }
    else if (blockIdx.y == 1) { in = k0; w = wk; bias = bk; out = kc; scale = 0.08838834764831845f; }
    else                      { in = v0; w = wv; bias = bv; out = vc; scale = 1.f; }

    const int c  = (i << 2) & (NC - 1);
    const int bt = (i << 2) >> 11;
    const int t  = bt & (NT - 1);

    const float4 w0 = ((const float4*)w)[c + 0];
    const float4 w1 = ((const float4*)w)[c + 1];
    const float4 w2 = ((const float4*)w)[c + 2];
    const float4 w3 = ((const float4*)w)[c + 3];
    const float* p = in + (size_t)bt * NC + c;

    float4 acc = *(const float4*)(bias + c);
    float4 xv = *(const float4*)p;
    acc.x = fmaf(w0.w, xv.x, acc.x); acc.y = fmaf(w1.w, xv.y, acc.y);
    acc.z = fmaf(w2.w, xv.z, acc.z); acc.w = fmaf(w3.w, xv.w, acc.w);
    if (t >= 1) {
        xv = *(const float4*)(p - NC);
        acc.x = fmaf(w0.z, xv.x, acc.x); acc.y = fmaf(w1.z, xv.y, acc.y);
        acc.z = fmaf(w2.z, xv.z, acc.z); acc.w = fmaf(w3.z, xv.w, acc.w);
    }
    if (t >= 2) {
        xv = *(const float4*)(p - 2 * NC);
        acc.x = fmaf(w0.y, xv.x, acc.x); acc.y = fmaf(w1.y, xv.y, acc.y);
        acc.z = fmaf(w2.y, xv.z, acc.z); acc.w = fmaf(w3.y, xv.w, acc.w);
    }
    if (t >= 3) {
        xv = *(const float4*)(p - 3 * NC);
        acc.x = fmaf(w0.x, xv.x, acc.x); acc.y = fmaf(w1.x, xv.y, acc.y);
        acc.z = fmaf(w2.x, xv.z, acc.z); acc.w = fmaf(w3.x, xv.w, acc.w);
    }
    float4 r;
    r.x = acc.x * fsig(acc.x) * scale;
    r.y = acc.y * fsig(acc.y) * scale;
    r.z = acc.z * fsig(acc.z) * scale;
    r.w = acc.w * fsig(acc.w) * scale;
    *(float4*)(out + (size_t)bt * NC + c) = r;
}

// ------------------------------------------------------------------
// Recurrence, v-split 8x: grid = B*H*8 = 256 blocks, 128 threads.
// Thread (vloc = tid>>3, kq = tid&7) owns S[vloc][kq*16 .. +15].
// Sk reduced over the 8 kq lanes (3 shfls). 8 o-partials per channel,
// summed in ln_gate_split.
// ------------------------------------------------------------------
__global__ void __launch_bounds__(128)
recur3(const float* __restrict__ qc, const float* __restrict__ kc,
       const float* __restrict__ vc, const float* __restrict__ ga,
       const float* __restrict__ gbeta, float* __restrict__ o8)
{
    const int bid  = blockIdx.x;          // 0..255
    const int b    = bid >> 7;
    const int h    = (bid >> 3) & 15;
    const int vblk = bid & 7;
    const int tid  = threadIdx.x;
    const int vloc = tid >> 3;            // 0..15
    const int kq   = tid & 7;             // 0..7

    __shared__ __align__(16) float sk[2][NDK];
    __shared__ __align__(16) float sq[2][NDK];

    float S[16];
#pragma unroll
    for (int j = 0; j < 16; j++) S[j] = 0.f;

    const int kchan = h * NDK + tid;                  // staging channel
    const int vchan = h * NDK + vblk * 16 + vloc;     // owned v channel
    const size_t tok0 = (size_t)b * NT;

    float k_cur = kc[tok0 * NC + kchan];
    float q_cur = qc[tok0 * NC + kchan];
    float v_cur = vc[tok0 * NC + vchan];
    float a_cur = ga[tok0 * NC + vchan];
    float be_cur = gbeta[tok0 * NH + h];

    for (int t = 0; t < NT; t++) {
        const int buf = t & 1;
        sk[buf][tid] = k_cur;
        sq[buf][tid] = q_cur;
        __syncthreads();

        float k_n = 0.f, q_n = 0.f, v_n = 0.f, a_n = 0.f, be_n = 0.f;
        if (t + 1 < NT) {
            const size_t idx = (tok0 + t + 1) * NC;
            k_n = kc[idx + kchan]; q_n = qc[idx + kchan];
            v_n = vc[idx + vchan]; a_n = ga[idx + vchan];
            be_n = gbeta[(tok0 + t + 1) * NH + h];
        }

        const float4* kb = (const float4*)&sk[buf][kq * 16];
        const float4* qb = (const float4*)&sq[buf][kq * 16];

        // Sk partial over this thread's 16 k's (4 accumulators, 4-deep)
        float p0 = 0.f, p1 = 0.f, p2 = 0.f, p3 = 0.f;
#pragma unroll
        for (int j = 0; j < 4; j++) {
            const float4 kk = kb[j];
            p0 = fmaf(S[4*j+0], kk.x, p0);
            p1 = fmaf(S[4*j+1], kk.y, p1);
            p2 = fmaf(S[4*j+2], kk.z, p2);
            p3 = fmaf(S[4*j+3], kk.w, p3);
        }
        float Sk = (p0 + p1) + (p2 + p3);
        Sk += __shfl_xor_sync(0xffffffffu, Sk, 1);
        Sk += __shfl_xor_sync(0xffffffffu, Sk, 2);
        Sk += __shfl_xor_sync(0xffffffffu, Sk, 4);

        const float coef = be_cur * (Sk - v_cur);
        const float a = a_cur;

        float o0 = 0.f, o1 = 0.f, o2 = 0.f, o3 = 0.f;
#pragma unroll
        for (int j = 0; j < 4; j++) {
            const float4 kk = kb[j];
            const float4 qq = qb[j];
            S[4*j+0] = fmaf(a, S[4*j+0], -coef * kk.x); o0 = fmaf(S[4*j+0], qq.x, o0);
            S[4*j+1] = fmaf(a, S[4*j+1], -coef * kk.y); o1 = fmaf(S[4*j+1], qq.y, o1);
            S[4*j+2] = fmaf(a, S[4*j+2], -coef * kk.z); o2 = fmaf(S[4*j+2], qq.z, o2);
            S[4*j+3] = fmaf(a, S[4*j+3], -coef * kk.w); o3 = fmaf(S[4*j+3], qq.w, o3);
        }
        const float op = (o0 + o1) + (o2 + o3);
        o8[((tok0 + t) * NC + vchan) * 8 + kq] = op;

        k_cur = k_n; q_cur = q_n; v_cur = v_n; a_cur = a_n; be_cur = be_n;
    }
}

// ------------------------------------------------------------------
// Sum 8 partials + LayerNorm + gate + bf16 split directly into g_xs.
// grid = NTOK*NH, block = 128
// ------------------------------------------------------------------
__global__ void __launch_bounds__(128)
ln_gate_split(const float* __restrict__ o8, const float* __restrict__ gg,
              const float* __restrict__ ln_g, const float* __restrict__ ln_b,
              __nv_bfloat16* __restrict__ xs)
{
    const int bid = blockIdx.x;
    const int tok = bid >> 4, h = bid & 15;
    const int v = threadIdx.x, lane = v & 31, wid = v >> 5;
    const int chan = h * NDK + v;
    const size_t idx = (size_t)tok * NC + chan;

    const float4 pa = ((const float4*)o8)[idx * 2];
    const float4 pb = ((const float4*)o8)[idx * 2 + 1];
    const float o = ((pa.x + pa.y) + (pa.z + pa.w))
                  + ((pb.x + pb.y) + (pb.z + pb.w));

    __shared__ float red[8];
    float rs = o, rs2 = o * o;
#pragma unroll
    for (int off = 16; off > 0; off >>= 1) {
        rs  += __shfl_xor_sync(0xffffffffu, rs,  off);
        rs2 += __shfl_xor_sync(0xffffffffu, rs2, off);
    }
    if (lane == 0) { red[wid] = rs; red[4 + wid] = rs2; }
    __syncthreads();
    const float mu  = (red[0] + red[1] + red[2] + red[3]) * (1.f / 128.f);
    const float ms  = (red[4] + red[5] + red[6] + red[7]) * (1.f / 128.f);
    const float var = ms - mu * mu;
    const float y = ((o - mu) * rsqrtf(var + 1e-5f) * ln_g[v] + ln_b[v]) * gg[idx];

    const __nv_bfloat16 hbf = __float2bfloat16(y);
    const __nv_bfloat16 lbf = __float2bfloat16(y - __bfloat162float(hbf));
    __nv_bfloat16* base = xs + (size_t)tok * KS + chan;
    base[0]    = hbf;
    base[2048] = lbf;
    base[4096] = hbf;
}

// ------------------------------------------------------------------
// Launch
// ------------------------------------------------------------------
extern "C" void kernel_launch(void* const* d_in, const int* in_sizes, int n_in,
                              void* d_out, int out_size)
{
    const float* x        = (const float*)d_in[0];
    const float* Wq       = (const float*)d_in[1];
    const float* Wk       = (const float*)d_in[2];
    const float* Wv       = (const float*)d_in[3];
    const float* Wa       = (const float*)d_in[4];
    const float* ba       = (const float*)d_in[5];
    const float* Wb       = (const float*)d_in[6];
    const float* bb       = (const float*)d_in[7];
    const float* conv_q_w = (const float*)d_in[8];
    const float* conv_q_b = (const float*)d_in[9];
    const float* conv_k_w = (const float*)d_in[10];
    const float* conv_k_b = (const float*)d_in[11];
    const float* conv_v_w = (const float*)d_in[12];
    const float* conv_v_b = (const float*)d_in[13];
    const float* Wg       = (const float*)d_in[14];
    const float* ln_g     = (const float*)d_in[15];
    const float* ln_b     = (const float*)d_in[16];
    const float* Wo       = (const float*)d_in[17];
    float* out = (float*)d_out;

    __nv_bfloat16 *xs, *ws;
    float *q0, *k0, *v0, *qc, *kc, *vc, *pa, *pg, *po8, *pbeta;
    cudaGetSymbolAddress((void**)&xs,    g_xs);
    cudaGetSymbolAddress((void**)&ws,    g_ws);
    cudaGetSymbolAddress((void**)&q0,    g_q0);
    cudaGetSymbolAddress((void**)&k0,    g_k0);
    cudaGetSymbolAddress((void**)&v0,    g_v0);
    cudaGetSymbolAddress((void**)&qc,    g_qc);
    cudaGetSymbolAddress((void**)&kc,    g_kc);
    cudaGetSymbolAddress((void**)&vc,    g_vc);
    cudaGetSymbolAddress((void**)&pa,    g_a);
    cudaGetSymbolAddress((void**)&pg,    g_gt);
    cudaGetSymbolAddress((void**)&po8,   g_o8);
    cudaGetSymbolAddress((void**)&pbeta, g_bt);

    static bool attr_set = false;
    if (!attr_set) {
        cudaFuncSetAttribute(tgemm, cudaFuncAttributeMaxDynamicSharedMemorySize, TG_SMEM);
        attr_set = true;
    }

    const int q4blk = ((NTOK * ND) / 4 + 255) / 256;   // 4096

    // all splits (x + 6 weights) in one launch; beta from fp32 x
    split_all<<<dim3(q4blk, 7), 256>>>(x, Wq, Wk, Wv, Wa, Wg, Wo, xs, ws);
    beta_k<<<NTOK, 256>>>(x, Wb, bb, pbeta);

    // fused 5-projection GEMM (q, k, v, a, g) — N = 10240
    tgemm<<<dim3(80, 16), 256, TG_SMEM>>>(xs, ws, ba, q0, k0, v0, pa, pg);

    // fused conv + silu (q, k*DK^-0.5, v)
    conv3<<<dim3(q4blk, 3), 256>>>(q0, k0, v0, conv_q_w, conv_k_w, conv_v_w,
                                   conv_q_b, conv_k_b, conv_v_b, qc, kc, vc);

    // recurrence (v-split 8x, deferred o-reduce) then LN + gate + split into xs
    recur3<<<NB * NH * 8, 128>>>(qc, kc, vc, pa, pbeta, po8);
    ln_gate_split<<<NTOK * NH, 128>>>(po8, pg, ln_g, ln_b, xs);

    // output projection (seg = 0 -> plain store to out)
    tgemm<<<dim3(16, 16), 256, TG_SMEM>>>(xs, ws + 5 * WSTRIDE, nullptr,
                                          out, out, out, out, out);
}

// round 7
// speedup vs baseline: 1.0371x; 1.0371x over previous
#include <cuda_runtime.h>
#include <cuda_bf16.h>
#include <math.h>
#include <stdint.h>

#define NB   2
#define NT   1024
#define ND   2048
#define NH   16
#define NDK  128
#define NTOK (NB*NT)      /* 2048 tokens */
#define NC   (NH*NDK)     /* 2048 channels */
#define KS   (3*ND)       /* 6144: split-precision K (hi|lo|hi) */
#define WSTRIDE ((size_t)NC*KS)

// ------------------------------------------------------------------
// Scratch (device globals; no runtime allocation allowed)
// ------------------------------------------------------------------
__device__ __nv_bfloat16 g_xs[(size_t)NTOK*KS];   // split activations
__device__ __nv_bfloat16 g_ws[6*WSTRIDE];         // 6 split weights (q,k,v,a,g,o)
__device__ float g_q0[NTOK*NC];
__device__ float g_k0[NTOK*NC];
__device__ float g_v0[NTOK*NC];
__device__ float g_qc[NTOK*NC];
__device__ float g_kc[NTOK*NC];
__device__ float g_vc[NTOK*NC];
__device__ float g_a [NTOK*NC];
__device__ float g_gt[NTOK*NC];
__device__ float g_o4[(size_t)NTOK*NC*4];         // 4 partial recurrence outputs / channel
__device__ float g_bt[NTOK*NH];

// ==================================================================
// Helpers
// ==================================================================
__device__ __forceinline__ uint32_t smem_u32(const void* p) {
    uint32_t r;
    asm("{ .reg .u64 t; cvta.to.shared.u64 t, %1; cvt.u32.u64 %0, t; }"
        : "=r"(r) : "l"(p));
    return r;
}
__device__ __forceinline__ void cp16(uint32_t dst, const void* src) {
    asm volatile("cp.async.cg.shared.global [%0], [%1], 16;\n" :: "r"(dst), "l"(src));
}
__device__ __forceinline__ void cp_commit() {
    asm volatile("cp.async.commit_group;\n" ::: "memory");
}
__device__ __forceinline__ void cp_wait1() {
    asm volatile("cp.async.wait_group 1;\n" ::: "memory");
}
__device__ __forceinline__ void cp_wait0() {
    asm volatile("cp.async.wait_group 0;\n" ::: "memory");
}
__device__ __forceinline__ void ldsm4(uint32_t& r0, uint32_t& r1, uint32_t& r2,
                                      uint32_t& r3, uint32_t addr) {
    asm volatile("ldmatrix.sync.aligned.m8n8.x4.shared.b16 {%0,%1,%2,%3}, [%4];"
                 : "=r"(r0), "=r"(r1), "=r"(r2), "=r"(r3) : "r"(addr));
}
__device__ __forceinline__ void mma16816(float* d, const uint32_t* a,
                                         uint32_t b0, uint32_t b1) {
    asm volatile(
        "mma.sync.aligned.m16n8k16.row.col.f32.bf16.bf16.f32 "
        "{%0,%1,%2,%3}, {%4,%5,%6,%7}, {%8,%9}, {%0,%1,%2,%3};"
        : "+f"(d[0]), "+f"(d[1]), "+f"(d[2]), "+f"(d[3])
        : "r"(a[0]), "r"(a[1]), "r"(a[2]), "r"(a[3]), "r"(b0), "r"(b1));
}
__device__ __forceinline__ float fsig(float z) {
    return 1.f / (1.f + __expf(-z));
}

// ==================================================================
// Tensor-core GEMM (HMMA): fused 5-projection (grid.x=80) or Wo (grid.x=16)
// 128x128 tile, BK=64, 3-stage cp.async pipeline, 8 warps, unroll-3 body.
// ==================================================================
#define BK      64
#define KITERS  (KS/BK)      /* 96 (divisible by 3) */
#define STG_B   32768
#define STAGES  3
#define TG_SMEM (STAGES*STG_B)

__global__ void __launch_bounds__(256, 2)
tgemm(const __nv_bfloat16* __restrict__ A, const __nv_bfloat16* __restrict__ Bw,
      const float* __restrict__ bias_a,
      float* __restrict__ Cq, float* __restrict__ Ck, float* __restrict__ Cv,
      float* __restrict__ Ca, float* __restrict__ Cg)
{
    extern __shared__ __align__(1024) char smem[];
    const uint32_t sb = smem_u32(smem);

    const int tid  = threadIdx.x;
    const int lane = tid & 31;
    const int wid  = tid >> 5;
    const int wm   = wid & 3;
    const int wn   = wid >> 2;
    const int m0   = blockIdx.y * 128;
    const int n0g  = blockIdx.x * 128;
    const int seg  = blockIdx.x >> 4;
    const int col0 = (blockIdx.x & 15) * 128;

    const int r0 = tid >> 3;
    const int c0 = tid & 7;
    const uint32_t stOff = (uint32_t)(((c0 ^ (r0 & 7)) << 4));

    const __nv_bfloat16* gA = A  + (size_t)(m0  + r0) * KS + c0 * 8;
    const __nv_bfloat16* gB = Bw + (size_t)(n0g + r0) * KS + c0 * 8;

    const int la = lane & 15, ha = lane >> 4;
    const int arow = wm * 32 + la;
    const uint32_t aswz = arow & 7;
    const int brow = wn * 64 + (lane & 7) + ((lane >> 4) & 1) * 8;
    const uint32_t bswz = brow & 7;
    const uint32_t bsel = (lane >> 3) & 1;

    uint32_t aoff[4], boff[4];
#pragma unroll
    for (int kh = 0; kh < 4; kh++) {
        aoff[kh] = arow * 128 + (((uint32_t)((2 * kh + ha) ^ aswz)) << 4);
        boff[kh] = 16384 + brow * 128 + (((uint32_t)((2 * kh + bsel) ^ bswz)) << 4);
    }

    float acc[2][8][4];
#pragma unroll
    for (int mi = 0; mi < 2; mi++)
#pragma unroll
        for (int ni = 0; ni < 8; ni++)
#pragma unroll
            for (int e = 0; e < 4; e++) acc[mi][ni][e] = 0.f;

#pragma unroll
    for (int s = 0; s < STAGES - 1; s++) {
        const uint32_t base = sb + s * STG_B;
        const int kc = s * BK;
#pragma unroll
        for (int r = 0; r < 4; r++) {
            const uint32_t so = (r0 + 32 * r) * 128 + stOff;
            cp16(base + so,         gA + (size_t)(32 * r) * KS + kc);
            cp16(base + 16384 + so, gB + (size_t)(32 * r) * KS + kc);
        }
        cp_commit();
    }

    for (int itb = 0; itb < KITERS; itb += 3) {
#pragma unroll
        for (int u = 0; u < 3; u++) {
            const int it = itb + u;
            if (it < KITERS - 1) cp_wait1(); else cp_wait0();
            __syncthreads();

            if (it + 2 < KITERS) {
                const uint32_t pbase = sb + ((u + 2) % 3) * STG_B;
                const int kc = (it + 2) * BK;
#pragma unroll
                for (int r = 0; r < 4; r++) {
                    const uint32_t so = (r0 + 32 * r) * 128 + stOff;
                    cp16(pbase + so,         gA + (size_t)(32 * r) * KS + kc);
                    cp16(pbase + 16384 + so, gB + (size_t)(32 * r) * KS + kc);
                }
            }
            cp_commit();

            const uint32_t base = sb + u * STG_B;

#pragma unroll
            for (int kh = 0; kh < 4; kh++) {
                uint32_t av[2][4];
                ldsm4(av[0][0], av[0][1], av[0][2], av[0][3], base + aoff[kh]);
                ldsm4(av[1][0], av[1][1], av[1][2], av[1][3], base + aoff[kh] + 2048);

                uint32_t bv[4][4];
#pragma unroll
                for (int p = 0; p < 4; p++)
                    ldsm4(bv[p][0], bv[p][1], bv[p][2], bv[p][3],
                          base + boff[kh] + p * 2048);

#pragma unroll
                for (int mi = 0; mi < 2; mi++)
#pragma unroll
                    for (int ni = 0; ni < 8; ni++) {
                        const int p = ni >> 1;
                        const int h = (ni & 1) * 2;
                        mma16816(acc[mi][ni], av[mi], bv[p][h], bv[p][h + 1]);
                    }
            }
        }
    }

    float* C = (seg == 0) ? Cq : (seg == 1) ? Ck : (seg == 2) ? Cv
             : (seg == 3) ? Ca : Cg;
    const int et = (seg == 3) ? 1 : (seg == 4) ? 2 : 0;

    const int g  = lane >> 2;
    const int tg = lane & 3;
#pragma unroll
    for (int mi = 0; mi < 2; mi++) {
        const int row = m0 + wm * 32 + mi * 16 + g;
#pragma unroll
        for (int ni = 0; ni < 8; ni++) {
            const int col = col0 + wn * 64 + ni * 8 + tg * 2;
            float v0 = acc[mi][ni][0], v1 = acc[mi][ni][1];
            float v2 = acc[mi][ni][2], v3 = acc[mi][ni][3];
            if (et == 1) {
                const float b0 = bias_a[col], b1 = bias_a[col + 1];
                v0 = fsig(v0 + b0); v1 = fsig(v1 + b1);
                v2 = fsig(v2 + b0); v3 = fsig(v3 + b1);
            } else if (et == 2) {
                v0 = fsig(v0); v1 = fsig(v1); v2 = fsig(v2); v3 = fsig(v3);
            }
            *(float2*)(C + (size_t)row * NC + col)       = make_float2(v0, v1);
            *(float2*)(C + (size_t)(row + 8) * NC + col) = make_float2(v2, v3);
        }
    }
}

// ------------------------------------------------------------------
// Split fp32 -> bf16 hi/lo, K-concatenated (float4 vectorized).
// ------------------------------------------------------------------
__device__ __forceinline__ void split_body(const float* __restrict__ in,
                                           __nv_bfloat16* __restrict__ out,
                                           int mode, int i)
{
    const int r  = i >> 9;
    const int k4 = (i << 2) & 2047;
    const float4 a = ((const float4*)in)[i];

    __nv_bfloat162 h01 = __floats2bfloat162_rn(a.x, a.y);
    __nv_bfloat162 h23 = __floats2bfloat162_rn(a.z, a.w);
    const float lx = a.x - __bfloat162float(__low2bfloat16(h01));
    const float ly = a.y - __bfloat162float(__high2bfloat16(h01));
    const float lz = a.z - __bfloat162float(__low2bfloat16(h23));
    const float lw = a.w - __bfloat162float(__high2bfloat16(h23));
    __nv_bfloat162 l01 = __floats2bfloat162_rn(lx, ly);
    __nv_bfloat162 l23 = __floats2bfloat162_rn(lz, lw);

    uint2 hp, lp;
    hp.x = *(const uint32_t*)&h01; hp.y = *(const uint32_t*)&h23;
    lp.x = *(const uint32_t*)&l01; lp.y = *(const uint32_t*)&l23;

    __nv_bfloat16* base = out + (size_t)r * KS + k4;
    *(uint2*)(base) = hp;
    if (mode == 0) { *(uint2*)(base + 2048) = lp; *(uint2*)(base + 4096) = hp; }
    else           { *(uint2*)(base + 2048) = hp; *(uint2*)(base + 4096) = lp; }
}

__global__ void __launch_bounds__(256)
split_all(const float* __restrict__ x,  const float* __restrict__ Wq,
          const float* __restrict__ Wk, const float* __restrict__ Wv,
          const float* __restrict__ Wa, const float* __restrict__ Wg,
          const float* __restrict__ Wo,
          __nv_bfloat16* __restrict__ xs, __nv_bfloat16* __restrict__ ws)
{
    const int i = blockIdx.x * 256 + threadIdx.x;
    if (i >= (NTOK * ND) / 4) return;
    const int which = blockIdx.y;
    if (which == 0)      split_body(x,  xs, 0, i);
    else if (which == 1) split_body(Wq, ws + 0 * WSTRIDE, 1, i);
    else if (which == 2) split_body(Wk, ws + 1 * WSTRIDE, 1, i);
    else if (which == 3) split_body(Wv, ws + 2 * WSTRIDE, 1, i);
    else if (which == 4) split_body(Wa, ws + 3 * WSTRIDE, 1, i);
    else if (which == 5) split_body(Wg, ws + 4 * WSTRIDE, 1, i);
    else                 split_body(Wo, ws + 5 * WSTRIDE, 1, i);
}

// ------------------------------------------------------------------
// beta = sigmoid(x @ Wb^T + bb)
// ------------------------------------------------------------------
__global__ void __launch_bounds__(256)
beta_k(const float* __restrict__ x, const float* __restrict__ Wb,
       const float* __restrict__ bb, float* __restrict__ out)
{
    __shared__ float xs[ND];
    const int row = blockIdx.x;
    for (int i = threadIdx.x; i < ND; i += 256) xs[i] = x[(size_t)row * ND + i];
    __syncthreads();
    const int w = threadIdx.x >> 5, lane = threadIdx.x & 31;
    for (int h = w; h < NH; h += 8) {
        const float* wr = Wb + (size_t)h * ND;
        float s = 0.f;
        for (int i = lane; i < ND; i += 32) s = fmaf(xs[i], wr[i], s);
#pragma unroll
        for (int o = 16; o > 0; o >>= 1) s += __shfl_xor_sync(0xffffffffu, s, o);
        if (lane == 0) out[(size_t)row * NH + h] = fsig(s + bb[h]);
    }
}

// ------------------------------------------------------------------
// Fused causal depthwise conv (K=4) + bias + silu + scale.
// 2 consecutive tokens per thread (5 row-loads -> 2 outputs).
// blockIdx.y: 0=q, 1=k (scaled), 2=v
// ------------------------------------------------------------------
__global__ void __launch_bounds__(256)
conv3(const float* __restrict__ q0, const float* __restrict__ k0,
      const float* __restrict__ v0,
      const float* __restrict__ wq, const float* __restrict__ wk,
      const float* __restrict__ wv,
      const float* __restrict__ bq, const float* __restrict__ bk,
      const float* __restrict__ bv,
      float* __restrict__ qc, float* __restrict__ kc, float* __restrict__ vc)
{
    const int i = blockIdx.x * 256 + threadIdx.x;
    if (i >= (NTOK / 2) * (NC / 4)) return;

    const float* in; const float* w; const float* bias; float* out; float scale;
    if (blockIdx.y == 0)      { in = q0; w = wq; bias = bq; out = qc; scale = 1.f; }
    else if (blockIdx.y == 1) { in = k0; w = wk; bias = bk; out = kc; scale = 0.08838834764831845f; }
    else                      { in = v0; w = wv; bias = bv; out = vc; scale = 1.f; }

    const int cg   = i & (NC / 4 - 1);       // channel group (4 channels)
    const int pair = i >> 9;                  // token pair index
    const int c    = cg * 4;
    const int t0   = (pair & (NT / 2 - 1)) * 2;
    const int b    = pair >> 9;

    const float4 w0 = ((const float4*)w)[c + 0];
    const float4 w1 = ((const float4*)w)[c + 1];
    const float4 w2 = ((const float4*)w)[c + 2];
    const float4 w3 = ((const float4*)w)[c + 3];
    const float4 bi = *(const float4*)(bias + c);

    const float* p = in + ((size_t)b * NT + t0) * NC + c;
    const float4 z = make_float4(0.f, 0.f, 0.f, 0.f);
    const float4 xm3 = (t0 >= 3) ? *(const float4*)(p - 3 * NC) : z;
    const float4 xm2 = (t0 >= 2) ? *(const float4*)(p - 2 * NC) : z;
    const float4 xm1 = (t0 >= 1) ? *(const float4*)(p - NC)     : z;
    const float4 x0  = *(const float4*)p;
    const float4 xp1 = *(const float4*)(p + NC);

    // out[t0] = bias + w.x*xm3 + w.y*xm2 + w.z*xm1 + w.w*x0
    float4 a0 = bi;
    a0.x = fmaf(w0.x, xm3.x, a0.x); a0.y = fmaf(w1.x, xm3.y, a0.y);
    a0.z = fmaf(w2.x, xm3.z, a0.z); a0.w = fmaf(w3.x, xm3.w, a0.w);
    a0.x = fmaf(w0.y, xm2.x, a0.x); a0.y = fmaf(w1.y, xm2.y, a0.y);
    a0.z = fmaf(w2.y, xm2.z, a0.z); a0.w = fmaf(w3.y, xm2.w, a0.w);
    a0.x = fmaf(w0.z, xm1.x, a0.x); a0.y = fmaf(w1.z, xm1.y, a0.y);
    a0.z = fmaf(w2.z, xm1.z, a0.z); a0.w = fmaf(w3.z, xm1.w, a0.w);
    a0.x = fmaf(w0.w, x0.x,  a0.x); a0.y = fmaf(w1.w, x0.y,  a0.y);
    a0.z = fmaf(w2.w, x0.z,  a0.z); a0.w = fmaf(w3.w, x0.w,  a0.w);

    // out[t0+1] = bias + w.x*xm2 + w.y*xm1 + w.z*x0 + w.w*xp1
    float4 a1 = bi;
    a1.x = fmaf(w0.x, xm2.x, a1.x); a1.y = fmaf(w1.x, xm2.y, a1.y);
    a1.z = fmaf(w2.x, xm2.z, a1.z); a1.w = fmaf(w3.x, xm2.w, a1.w);
    a1.x = fmaf(w0.y, xm1.x, a1.x); a1.y = fmaf(w1.y, xm1.y, a1.y);
    a1.z = fmaf(w2.y, xm1.z, a1.z); a1.w = fmaf(w3.y, xm1.w, a1.w);
    a1.x = fmaf(w0.z, x0.x,  a1.x); a1.y = fmaf(w1.z, x0.y,  a1.y);
    a1.z = fmaf(w2.z, x0.z,  a1.z); a1.w = fmaf(w3.z, x0.w,  a1.w);
    a1.x = fmaf(w0.w, xp1.x, a1.x); a1.y = fmaf(w1.w, xp1.y, a1.y);
    a1.z = fmaf(w2.w, xp1.z, a1.z); a1.w = fmaf(w3.w, xp1.w, a1.w);

    float4 r0o, r1o;
    r0o.x = a0.x * fsig(a0.x) * scale; r0o.y = a0.y * fsig(a0.y) * scale;
    r0o.z = a0.z * fsig(a0.z) * scale; r0o.w = a0.w * fsig(a0.w) * scale;
    r1o.x = a1.x * fsig(a1.x) * scale; r1o.y = a1.y * fsig(a1.y) * scale;
    r1o.z = a1.z * fsig(a1.z) * scale; r1o.w = a1.w * fsig(a1.w) * scale;

    float* po = out + ((size_t)b * NT + t0) * NC + c;
    *(float4*)po        = r0o;
    *(float4*)(po + NC) = r1o;
}

// ------------------------------------------------------------------
// Recurrence, v-split 4x (R5 config): grid = B*H*4, 128 threads.
// Thread (vloc = tid>>2, kq = tid&3) owns S[vloc][kq*32 .. +31].
// ------------------------------------------------------------------
__global__ void __launch_bounds__(128)
recur2(const float* __restrict__ qc, const float* __restrict__ kc,
       const float* __restrict__ vc, const float* __restrict__ ga,
       const float* __restrict__ gbeta, float* __restrict__ o4)
{
    const int bid  = blockIdx.x;
    const int b    = bid >> 6;
    const int h    = (bid >> 2) & 15;
    const int vblk = bid & 3;
    const int tid  = threadIdx.x;
    const int vloc = tid >> 2;
    const int kq   = tid & 3;

    __shared__ __align__(16) float sk[2][160];
    __shared__ __align__(16) float sq[2][160];

    float S[32];
#pragma unroll
    for (int j = 0; j < 32; j++) S[j] = 0.f;

    const int kchan = h * NDK + tid;
    const int vchan = h * NDK + vblk * 32 + vloc;
    const int sidx  = (tid >> 5) * 40 + (tid & 31);
    const size_t tok0 = (size_t)b * NT;

    float k_cur = kc[tok0 * NC + kchan];
    float q_cur = qc[tok0 * NC + kchan];
    float v_cur = vc[tok0 * NC + vchan];
    float a_cur = ga[tok0 * NC + vchan];
    float be_cur = gbeta[tok0 * NH + h];

    for (int t = 0; t < NT; t++) {
        const int buf = t & 1;
        sk[buf][sidx] = k_cur;
        sq[buf][sidx] = q_cur;
        __syncthreads();

        float k_n = 0.f, q_n = 0.f, v_n = 0.f, a_n = 0.f, be_n = 0.f;
        if (t + 1 < NT) {
            const size_t idx = (tok0 + t + 1) * NC;
            k_n = kc[idx + kchan]; q_n = qc[idx + kchan];
            v_n = vc[idx + vchan]; a_n = ga[idx + vchan];
            be_n = gbeta[(tok0 + t + 1) * NH + h];
        }

        const float4* kb = (const float4*)&sk[buf][kq * 40];
        const float4* qb = (const float4*)&sq[buf][kq * 40];

        float p0 = 0.f, p1 = 0.f, p2 = 0.f, p3 = 0.f;
        float p4 = 0.f, p5 = 0.f, p6 = 0.f, p7 = 0.f;
#pragma unroll
        for (int j = 0; j < 4; j++) {
            const float4 ka = kb[2 * j];
            const float4 kc2 = kb[2 * j + 1];
            p0 = fmaf(S[8*j+0], ka.x,  p0);
            p1 = fmaf(S[8*j+1], ka.y,  p1);
            p2 = fmaf(S[8*j+2], ka.z,  p2);
            p3 = fmaf(S[8*j+3], ka.w,  p3);
            p4 = fmaf(S[8*j+4], kc2.x, p4);
            p5 = fmaf(S[8*j+5], kc2.y, p5);
            p6 = fmaf(S[8*j+6], kc2.z, p6);
            p7 = fmaf(S[8*j+7], kc2.w, p7);
        }
        float Sk = ((p0 + p1) + (p2 + p3)) + ((p4 + p5) + (p6 + p7));
        Sk += __shfl_xor_sync(0xffffffffu, Sk, 1);
        Sk += __shfl_xor_sync(0xffffffffu, Sk, 2);

        const float coef = be_cur * (Sk - v_cur);
        const float a = a_cur;

        float o0 = 0.f, o1 = 0.f, o2 = 0.f, o3 = 0.f;
        float o4r = 0.f, o5 = 0.f, o6 = 0.f, o7 = 0.f;
#pragma unroll
        for (int j = 0; j < 4; j++) {
            const float4 ka  = kb[2 * j];
            const float4 kc2 = kb[2 * j + 1];
            const float4 qa  = qb[2 * j];
            const float4 qc2 = qb[2 * j + 1];
            S[8*j+0] = fmaf(a, S[8*j+0], -coef * ka.x);  o0  = fmaf(S[8*j+0], qa.x,  o0);
            S[8*j+1] = fmaf(a, S[8*j+1], -coef * ka.y);  o1  = fmaf(S[8*j+1], qa.y,  o1);
            S[8*j+2] = fmaf(a, S[8*j+2], -coef * ka.z);  o2  = fmaf(S[8*j+2], qa.z,  o2);
            S[8*j+3] = fmaf(a, S[8*j+3], -coef * ka.w);  o3  = fmaf(S[8*j+3], qa.w,  o3);
            S[8*j+4] = fmaf(a, S[8*j+4], -coef * kc2.x); o4r = fmaf(S[8*j+4], qc2.x, o4r);
            S[8*j+5] = fmaf(a, S[8*j+5], -coef * kc2.y); o5  = fmaf(S[8*j+5], qc2.y, o5);
            S[8*j+6] = fmaf(a, S[8*j+6], -coef * kc2.z); o6  = fmaf(S[8*j+6], qc2.z, o6);
            S[8*j+7] = fmaf(a, S[8*j+7], -coef * kc2.w); o7  = fmaf(S[8*j+7], qc2.w, o7);
        }
        const float op = ((o0 + o1) + (o2 + o3)) + ((o4r + o5) + (o6 + o7));
        o4[((tok0 + t) * NC + vchan) * 4 + kq] = op;

        k_cur = k_n; q_cur = q_n; v_cur = v_n; a_cur = a_n; be_cur = be_n;
    }
}

// ------------------------------------------------------------------
// Sum 4 partials + LayerNorm + gate + bf16 split directly into g_xs.
// ------------------------------------------------------------------
__global__ void __launch_bounds__(128)
ln_gate_split(const float* __restrict__ o4, const float* __restrict__ gg,
              const float* __restrict__ ln_g, const float* __restrict__ ln_b,
              __nv_bfloat16* __restrict__ xs)
{
    const int bid = blockIdx.x;
    const int tok = bid >> 4, h = bid & 15;
    const int v = threadIdx.x, lane = v & 31, wid = v >> 5;
    const int chan = h * NDK + v;
    const size_t idx = (size_t)tok * NC + chan;

    const float4 part = ((const float4*)o4)[idx];
    const float o = (part.x + part.y) + (part.z + part.w);

    __shared__ float red[8];
    float rs = o, rs2 = o * o;
#pragma unroll
    for (int off = 16; off > 0; off >>= 1) {
        rs  += __shfl_xor_sync(0xffffffffu, rs,  off);
        rs2 += __shfl_xor_sync(0xffffffffu, rs2, off);
    }
    if (lane == 0) { red[wid] = rs; red[4 + wid] = rs2; }
    __syncthreads();
    const float mu  = (red[0] + red[1] + red[2] + red[3]) * (1.f / 128.f);
    const float ms  = (red[4] + red[5] + red[6] + red[7]) * (1.f / 128.f);
    const float var = ms - mu * mu;
    const float y = ((o - mu) * rsqrtf(var + 1e-5f) * ln_g[v] + ln_b[v]) * gg[idx];

    const __nv_bfloat16 hbf = __float2bfloat16(y);
    const __nv_bfloat16 lbf = __float2bfloat16(y - __bfloat162float(hbf));
    __nv_bfloat16* base = xs + (size_t)tok * KS + chan;
    base[0]    = hbf;
    base[2048] = lbf;
    base[4096] = hbf;
}

// ------------------------------------------------------------------
// Launch
// ------------------------------------------------------------------
extern "C" void kernel_launch(void* const* d_in, const int* in_sizes, int n_in,
                              void* d_out, int out_size)
{
    const float* x        = (const float*)d_in[0];
    const float* Wq       = (const float*)d_in[1];
    const float* Wk       = (const float*)d_in[2];
    const float* Wv       = (const float*)d_in[3];
    const float* Wa       = (const float*)d_in[4];
    const float* ba       = (const float*)d_in[5];
    const float* Wb       = (const float*)d_in[6];
    const float* bb       = (const float*)d_in[7];
    const float* conv_q_w = (const float*)d_in[8];
    const float* conv_q_b = (const float*)d_in[9];
    const float* conv_k_w = (const float*)d_in[10];
    const float* conv_k_b = (const float*)d_in[11];
    const float* conv_v_w = (const float*)d_in[12];
    const float* conv_v_b = (const float*)d_in[13];
    const float* Wg       = (const float*)d_in[14];
    const float* ln_g     = (const float*)d_in[15];
    const float* ln_b     = (const float*)d_in[16];
    const float* Wo       = (const float*)d_in[17];
    float* out = (float*)d_out;

    __nv_bfloat16 *xs, *ws;
    float *q0, *k0, *v0, *qc, *kc, *vc, *pa, *pg, *po4, *pbeta;
    cudaGetSymbolAddress((void**)&xs,    g_xs);
    cudaGetSymbolAddress((void**)&ws,    g_ws);
    cudaGetSymbolAddress((void**)&q0,    g_q0);
    cudaGetSymbolAddress((void**)&k0,    g_k0);
    cudaGetSymbolAddress((void**)&v0,    g_v0);
    cudaGetSymbolAddress((void**)&qc,    g_qc);
    cudaGetSymbolAddress((void**)&kc,    g_kc);
    cudaGetSymbolAddress((void**)&vc,    g_vc);
    cudaGetSymbolAddress((void**)&pa,    g_a);
    cudaGetSymbolAddress((void**)&pg,    g_gt);
    cudaGetSymbolAddress((void**)&po4,   g_o4);
    cudaGetSymbolAddress((void**)&pbeta, g_bt);

    static bool attr_set = false;
    if (!attr_set) {
        cudaFuncSetAttribute(tgemm, cudaFuncAttributeMaxDynamicSharedMemorySize, TG_SMEM);
        attr_set = true;
    }

    const int q4blk = ((NTOK * ND) / 4 + 255) / 256;     // 4096
    const int c2blk = ((NTOK / 2) * (NC / 4) + 255) / 256; // 2048

    // all splits (x + 6 weights) in one launch; beta from fp32 x
    split_all<<<dim3(q4blk, 7), 256>>>(x, Wq, Wk, Wv, Wa, Wg, Wo, xs, ws);
    beta_k<<<NTOK, 256>>>(x, Wb, bb, pbeta);

    // fused 5-projection GEMM (q, k, v, a, g) — N = 10240
    tgemm<<<dim3(80, 16), 256, TG_SMEM>>>(xs, ws, ba, q0, k0, v0, pa, pg);

    // fused conv + silu (q, k*DK^-0.5, v), 2 tokens per thread
    conv3<<<dim3(c2blk, 3), 256>>>(q0, k0, v0, conv_q_w, conv_k_w, conv_v_w,
                                   conv_q_b, conv_k_b, conv_v_b, qc, kc, vc);

    // recurrence (v-split 4x, deferred o-reduce) then LN + gate + split into xs
    recur2<<<NB * NH * 4, 128>>>(qc, kc, vc, pa, pbeta, po4);
    ln_gate_split<<<NTOK * NH, 128>>>(po4, pg, ln_g, ln_b, xs);

    // output projection (seg = 0 -> plain store to out)
    tgemm<<<dim3(16, 16), 256, TG_SMEM>>>(xs, ws + 5 * WSTRIDE, nullptr,
                                          out, out, out, out, out);
}

// round 8
// speedup vs baseline: 1.1628x; 1.1212x over previous
#include <cuda_runtime.h>
#include <cuda_bf16.h>
#include <math.h>
#include <stdint.h>

#define NB   2
#define NT   1024
#define ND   2048
#define NH   16
#define NDK  128
#define NTOK (NB*NT)      /* 2048 tokens */
#define NC   (NH*NDK)     /* 2048 channels */
#define KS   (3*ND)       /* 6144: split-precision K (hi|lo|hi) */
#define WSTRIDE ((size_t)NC*KS)

// ------------------------------------------------------------------
// Scratch (device globals; no runtime allocation allowed)
// ------------------------------------------------------------------
__device__ __nv_bfloat16 g_xs[(size_t)NTOK*KS];   // split activations
__device__ __nv_bfloat16 g_ws[6*WSTRIDE];         // 6 split weights (q,k,v,a,g,o)
__device__ float g_q0[NTOK*NC];
__device__ float g_k0[NTOK*NC];
__device__ float g_v0[NTOK*NC];
__device__ float g_qc[NTOK*NC];
__device__ float g_kc[NTOK*NC];
__device__ float g_vc[NTOK*NC];
__device__ float g_a [NTOK*NC];
__device__ float g_gt[NTOK*NC];
__device__ float g_o4[(size_t)NTOK*NC*4];         // 4 partial recurrence outputs / channel
__device__ float g_bt[NTOK*NH];

// ==================================================================
// Helpers
// ==================================================================
__device__ __forceinline__ uint32_t smem_u32(const void* p) {
    uint32_t r;
    asm("{ .reg .u64 t; cvta.to.shared.u64 t, %1; cvt.u32.u64 %0, t; }"
        : "=r"(r) : "l"(p));
    return r;
}
__device__ __forceinline__ void cp16(uint32_t dst, const void* src) {
    asm volatile("cp.async.cg.shared.global [%0], [%1], 16;\n" :: "r"(dst), "l"(src));
}
__device__ __forceinline__ void cp_commit() {
    asm volatile("cp.async.commit_group;\n" ::: "memory");
}
__device__ __forceinline__ void cp_wait1() {
    asm volatile("cp.async.wait_group 1;\n" ::: "memory");
}
__device__ __forceinline__ void cp_wait0() {
    asm volatile("cp.async.wait_group 0;\n" ::: "memory");
}
__device__ __forceinline__ void ldsm4(uint32_t& r0, uint32_t& r1, uint32_t& r2,
                                      uint32_t& r3, uint32_t addr) {
    asm volatile("ldmatrix.sync.aligned.m8n8.x4.shared.b16 {%0,%1,%2,%3}, [%4];"
                 : "=r"(r0), "=r"(r1), "=r"(r2), "=r"(r3) : "r"(addr));
}
__device__ __forceinline__ void mma16816(float* d, const uint32_t* a,
                                         uint32_t b0, uint32_t b1) {
    asm volatile(
        "mma.sync.aligned.m16n8k16.row.col.f32.bf16.bf16.f32 "
        "{%0,%1,%2,%3}, {%4,%5,%6,%7}, {%8,%9}, {%0,%1,%2,%3};"
        : "+f"(d[0]), "+f"(d[1]), "+f"(d[2]), "+f"(d[3])
        : "r"(a[0]), "r"(a[1]), "r"(a[2]), "r"(a[3]), "r"(b0), "r"(b1));
}
__device__ __forceinline__ float fsig(float z) {
    return 1.f / (1.f + __expf(-z));
}

// ==================================================================
// Tensor-core GEMM (HMMA): fused 5-projection (grid.x=80) or Wo (grid.x=16)
// 128x128 tile, BK=64, 3-stage cp.async pipeline (96 KB smem), 8 warps.
// (R5 configuration — verbatim; known-good local optimum.)
// ==================================================================
#define BK      64
#define KITERS  (KS/BK)      /* 96 */
#define STG_B   32768
#define STAGES  3
#define TG_SMEM (STAGES*STG_B)

__global__ void __launch_bounds__(256, 2)
tgemm(const __nv_bfloat16* __restrict__ A, const __nv_bfloat16* __restrict__ Bw,
      const float* __restrict__ bias_a,
      float* __restrict__ Cq, float* __restrict__ Ck, float* __restrict__ Cv,
      float* __restrict__ Ca, float* __restrict__ Cg)
{
    extern __shared__ __align__(1024) char smem[];
    const uint32_t sb = smem_u32(smem);

    const int tid  = threadIdx.x;
    const int lane = tid & 31;
    const int wid  = tid >> 5;
    const int wm   = wid & 3;
    const int wn   = wid >> 2;
    const int m0   = blockIdx.y * 128;
    const int n0g  = blockIdx.x * 128;
    const int seg  = blockIdx.x >> 4;
    const int col0 = (blockIdx.x & 15) * 128;

    const int r0 = tid >> 3;
    const int c0 = tid & 7;
    const uint32_t stOff = (uint32_t)(((c0 ^ (r0 & 7)) << 4));

    const __nv_bfloat16* gA = A  + (size_t)(m0  + r0) * KS + c0 * 8;
    const __nv_bfloat16* gB = Bw + (size_t)(n0g + r0) * KS + c0 * 8;

    const int la = lane & 15, ha = lane >> 4;
    const int arow = wm * 32 + la;
    const uint32_t aswz = arow & 7;
    const int brow = wn * 64 + (lane & 7) + ((lane >> 4) & 1) * 8;
    const uint32_t bswz = brow & 7;
    const uint32_t bsel = (lane >> 3) & 1;

    uint32_t aoff[4], boff[4];
#pragma unroll
    for (int kh = 0; kh < 4; kh++) {
        aoff[kh] = arow * 128 + (((uint32_t)((2 * kh + ha) ^ aswz)) << 4);
        boff[kh] = 16384 + brow * 128 + (((uint32_t)((2 * kh + bsel) ^ bswz)) << 4);
    }

    float acc[2][8][4];
#pragma unroll
    for (int mi = 0; mi < 2; mi++)
#pragma unroll
        for (int ni = 0; ni < 8; ni++)
#pragma unroll
            for (int e = 0; e < 4; e++) acc[mi][ni][e] = 0.f;

#pragma unroll
    for (int s = 0; s < STAGES - 1; s++) {
        const uint32_t base = sb + s * STG_B;
        const int kc = s * BK;
#pragma unroll
        for (int r = 0; r < 4; r++) {
            const uint32_t so = (r0 + 32 * r) * 128 + stOff;
            cp16(base + so,         gA + (size_t)(32 * r) * KS + kc);
            cp16(base + 16384 + so, gB + (size_t)(32 * r) * KS + kc);
        }
        cp_commit();
    }

    int stage = 0;
    for (int it = 0; it < KITERS; it++) {
        if (it < KITERS - 1) cp_wait1(); else cp_wait0();
        __syncthreads();

        if (it + 2 < KITERS) {
            const int ps = (stage + 2 >= STAGES) ? stage + 2 - STAGES : stage + 2;
            const uint32_t base = sb + ps * STG_B;
            const int kc = (it + 2) * BK;
#pragma unroll
            for (int r = 0; r < 4; r++) {
                const uint32_t so = (r0 + 32 * r) * 128 + stOff;
                cp16(base + so,         gA + (size_t)(32 * r) * KS + kc);
                cp16(base + 16384 + so, gB + (size_t)(32 * r) * KS + kc);
            }
        }
        cp_commit();

        const uint32_t base = sb + stage * STG_B;
        stage = (stage + 1 >= STAGES) ? 0 : stage + 1;

#pragma unroll
        for (int kh = 0; kh < 4; kh++) {
            uint32_t av[2][4];
            ldsm4(av[0][0], av[0][1], av[0][2], av[0][3], base + aoff[kh]);
            ldsm4(av[1][0], av[1][1], av[1][2], av[1][3], base + aoff[kh] + 2048);

            uint32_t bv[4][4];
#pragma unroll
            for (int p = 0; p < 4; p++)
                ldsm4(bv[p][0], bv[p][1], bv[p][2], bv[p][3],
                      base + boff[kh] + p * 2048);

#pragma unroll
            for (int mi = 0; mi < 2; mi++)
#pragma unroll
                for (int ni = 0; ni < 8; ni++) {
                    const int p = ni >> 1;
                    const int h = (ni & 1) * 2;
                    mma16816(acc[mi][ni], av[mi], bv[p][h], bv[p][h + 1]);
                }
        }
    }

    float* C = (seg == 0) ? Cq : (seg == 1) ? Ck : (seg == 2) ? Cv
             : (seg == 3) ? Ca : Cg;
    const int et = (seg == 3) ? 1 : (seg == 4) ? 2 : 0;

    const int g  = lane >> 2;
    const int tg = lane & 3;
#pragma unroll
    for (int mi = 0; mi < 2; mi++) {
        const int row = m0 + wm * 32 + mi * 16 + g;
#pragma unroll
        for (int ni = 0; ni < 8; ni++) {
            const int col = col0 + wn * 64 + ni * 8 + tg * 2;
            float v0 = acc[mi][ni][0], v1 = acc[mi][ni][1];
            float v2 = acc[mi][ni][2], v3 = acc[mi][ni][3];
            if (et == 1) {
                const float b0 = bias_a[col], b1 = bias_a[col + 1];
                v0 = fsig(v0 + b0); v1 = fsig(v1 + b1);
                v2 = fsig(v2 + b0); v3 = fsig(v3 + b1);
            } else if (et == 2) {
                v0 = fsig(v0); v1 = fsig(v1); v2 = fsig(v2); v3 = fsig(v3);
            }
            *(float2*)(C + (size_t)row * NC + col)       = make_float2(v0, v1);
            *(float2*)(C + (size_t)(row + 8) * NC + col) = make_float2(v2, v3);
        }
    }
}

// ------------------------------------------------------------------
// Split fp32 -> bf16 hi/lo, K-concatenated (float4 vectorized).
// ------------------------------------------------------------------
__device__ __forceinline__ void split_body(const float* __restrict__ in,
                                           __nv_bfloat16* __restrict__ out,
                                           int mode, int i)
{
    const int r  = i >> 9;
    const int k4 = (i << 2) & 2047;
    const float4 a = ((const float4*)in)[i];

    __nv_bfloat162 h01 = __floats2bfloat162_rn(a.x, a.y);
    __nv_bfloat162 h23 = __floats2bfloat162_rn(a.z, a.w);
    const float lx = a.x - __bfloat162float(__low2bfloat16(h01));
    const float ly = a.y - __bfloat162float(__high2bfloat16(h01));
    const float lz = a.z - __bfloat162float(__low2bfloat16(h23));
    const float lw = a.w - __bfloat162float(__high2bfloat16(h23));
    __nv_bfloat162 l01 = __floats2bfloat162_rn(lx, ly);
    __nv_bfloat162 l23 = __floats2bfloat162_rn(lz, lw);

    uint2 hp, lp;
    hp.x = *(const uint32_t*)&h01; hp.y = *(const uint32_t*)&h23;
    lp.x = *(const uint32_t*)&l01; lp.y = *(const uint32_t*)&l23;

    __nv_bfloat16* base = out + (size_t)r * KS + k4;
    *(uint2*)(base) = hp;
    if (mode == 0) { *(uint2*)(base + 2048) = lp; *(uint2*)(base + 4096) = hp; }
    else           { *(uint2*)(base + 2048) = hp; *(uint2*)(base + 4096) = lp; }
}

__global__ void __launch_bounds__(256)
split_all(const float* __restrict__ x,  const float* __restrict__ Wq,
          const float* __restrict__ Wk, const float* __restrict__ Wv,
          const float* __restrict__ Wa, const float* __restrict__ Wg,
          const float* __restrict__ Wo,
          __nv_bfloat16* __restrict__ xs, __nv_bfloat16* __restrict__ ws)
{
    const int i = blockIdx.x * 256 + threadIdx.x;
    if (i >= (NTOK * ND) / 4) return;
    const int which = blockIdx.y;
    if (which == 0)      split_body(x,  xs, 0, i);
    else if (which == 1) split_body(Wq, ws + 0 * WSTRIDE, 1, i);
    else if (which == 2) split_body(Wk, ws + 1 * WSTRIDE, 1, i);
    else if (which == 3) split_body(Wv, ws + 2 * WSTRIDE, 1, i);
    else if (which == 4) split_body(Wa, ws + 3 * WSTRIDE, 1, i);
    else if (which == 5) split_body(Wg, ws + 4 * WSTRIDE, 1, i);
    else                 split_body(Wo, ws + 5 * WSTRIDE, 1, i);
}

// ------------------------------------------------------------------
// beta = sigmoid(x @ Wb^T + bb)
// ------------------------------------------------------------------
__global__ void __launch_bounds__(256)
beta_k(const float* __restrict__ x, const float* __restrict__ Wb,
       const float* __restrict__ bb, float* __restrict__ out)
{
    __shared__ float xs[ND];
    const int row = blockIdx.x;
    for (int i = threadIdx.x; i < ND; i += 256) xs[i] = x[(size_t)row * ND + i];
    __syncthreads();
    const int w = threadIdx.x >> 5, lane = threadIdx.x & 31;
    for (int h = w; h < NH; h += 8) {
        const float* wr = Wb + (size_t)h * ND;
        float s = 0.f;
        for (int i = lane; i < ND; i += 32) s = fmaf(xs[i], wr[i], s);
#pragma unroll
        for (int o = 16; o > 0; o >>= 1) s += __shfl_xor_sync(0xffffffffu, s, o);
        if (lane == 0) out[(size_t)row * NH + h] = fsig(s + bb[h]);
    }
}

// ------------------------------------------------------------------
// Fused causal depthwise conv (K=4) + bias + silu + scale.
// 2 consecutive tokens per thread (5 row-loads -> 2 outputs).
// ------------------------------------------------------------------
__global__ void __launch_bounds__(256)
conv3(const float* __restrict__ q0, const float* __restrict__ k0,
      const float* __restrict__ v0,
      const float* __restrict__ wq, const float* __restrict__ wk,
      const float* __restrict__ wv,
      const float* __restrict__ bq, const float* __restrict__ bk,
      const float* __restrict__ bv,
      float* __restrict__ qc, float* __restrict__ kc, float* __restrict__ vc)
{
    const int i = blockIdx.x * 256 + threadIdx.x;
    if (i >= (NTOK / 2) * (NC / 4)) return;

    const float* in; const float* w; const float* bias; float* out; float scale;
    if (blockIdx.y == 0)      { in = q0; w = wq; bias = bq; out = qc; scale = 1.f; }
    else if (blockIdx.y == 1) { in = k0; w = wk; bias = bk; out = kc; scale = 0.08838834764831845f; }
    else                      { in = v0; w = wv; bias = bv; out = vc; scale = 1.f; }

    const int cg   = i & (NC / 4 - 1);
    const int pair = i >> 9;
    const int c    = cg * 4;
    const int t0   = (pair & (NT / 2 - 1)) * 2;
    const int b    = pair >> 9;

    const float4 w0 = ((const float4*)w)[c + 0];
    const float4 w1 = ((const float4*)w)[c + 1];
    const float4 w2 = ((const float4*)w)[c + 2];
    const float4 w3 = ((const float4*)w)[c + 3];
    const float4 bi = *(const float4*)(bias + c);

    const float* p = in + ((size_t)b * NT + t0) * NC + c;
    const float4 z = make_float4(0.f, 0.f, 0.f, 0.f);
    const float4 xm3 = (t0 >= 3) ? *(const float4*)(p - 3 * NC) : z;
    const float4 xm2 = (t0 >= 2) ? *(const float4*)(p - 2 * NC) : z;
    const float4 xm1 = (t0 >= 1) ? *(const float4*)(p - NC)     : z;
    const float4 x0  = *(const float4*)p;
    const float4 xp1 = *(const float4*)(p + NC);

    float4 a0 = bi;
    a0.x = fmaf(w0.x, xm3.x, a0.x); a0.y = fmaf(w1.x, xm3.y, a0.y);
    a0.z = fmaf(w2.x, xm3.z, a0.z); a0.w = fmaf(w3.x, xm3.w, a0.w);
    a0.x = fmaf(w0.y, xm2.x, a0.x); a0.y = fmaf(w1.y, xm2.y, a0.y);
    a0.z = fmaf(w2.y, xm2.z, a0.z); a0.w = fmaf(w3.y, xm2.w, a0.w);
    a0.x = fmaf(w0.z, xm1.x, a0.x); a0.y = fmaf(w1.z, xm1.y, a0.y);
    a0.z = fmaf(w2.z, xm1.z, a0.z); a0.w = fmaf(w3.z, xm1.w, a0.w);
    a0.x = fmaf(w0.w, x0.x,  a0.x); a0.y = fmaf(w1.w, x0.y,  a0.y);
    a0.z = fmaf(w2.w, x0.z,  a0.z); a0.w = fmaf(w3.w, x0.w,  a0.w);

    float4 a1 = bi;
    a1.x = fmaf(w0.x, xm2.x, a1.x); a1.y = fmaf(w1.x, xm2.y, a1.y);
    a1.z = fmaf(w2.x, xm2.z, a1.z); a1.w = fmaf(w3.x, xm2.w, a1.w);
    a1.x = fmaf(w0.y, xm1.x, a1.x); a1.y = fmaf(w1.y, xm1.y, a1.y);
    a1.z = fmaf(w2.y, xm1.z, a1.z); a1.w = fmaf(w3.y, xm1.w, a1.w);
    a1.x = fmaf(w0.z, x0.x,  a1.x); a1.y = fmaf(w1.z, x0.y,  a1.y);
    a1.z = fmaf(w2.z, x0.z,  a1.z); a1.w = fmaf(w3.z, x0.w,  a1.w);
    a1.x = fmaf(w0.w, xp1.x, a1.x); a1.y = fmaf(w1.w, xp1.y, a1.y);
    a1.z = fmaf(w2.w, xp1.z, a1.z); a1.w = fmaf(w3.w, xp1.w, a1.w);

    float4 r0o, r1o;
    r0o.x = a0.x * fsig(a0.x) * scale; r0o.y = a0.y * fsig(a0.y) * scale;
    r0o.z = a0.z * fsig(a0.z) * scale; r0o.w = a0.w * fsig(a0.w) * scale;
    r1o.x = a1.x * fsig(a1.x) * scale; r1o.y = a1.y * fsig(a1.y) * scale;
    r1o.z = a1.z * fsig(a1.z) * scale; r1o.w = a1.w * fsig(a1.w) * scale;

    float* po = out + ((size_t)b * NT + t0) * NC + c;
    *(float4*)po        = r0o;
    *(float4*)(po + NC) = r1o;
}

// ------------------------------------------------------------------
// Recurrence, v-split 4x, 4-buffer staging, one __syncthreads per 2 steps.
// Thread (vloc = tid>>2, kq = tid&3) owns S[vloc][kq*32 .. +31].
// ------------------------------------------------------------------
__global__ void __launch_bounds__(128)
recur2(const float* __restrict__ qc, const float* __restrict__ kc,
       const float* __restrict__ vc, const float* __restrict__ ga,
       const float* __restrict__ gbeta, float* __restrict__ o4)
{
    const int bid  = blockIdx.x;
    const int b    = bid >> 6;
    const int h    = (bid >> 2) & 15;
    const int vblk = bid & 3;
    const int tid  = threadIdx.x;
    const int vloc = tid >> 2;
    const int kq   = tid & 3;

    __shared__ __align__(16) float sk[4][160];
    __shared__ __align__(16) float sq[4][160];

    float S[32];
#pragma unroll
    for (int j = 0; j < 32; j++) S[j] = 0.f;

    const int kchan = h * NDK + tid;
    const int vchan = h * NDK + vblk * 32 + vloc;
    const int sidx  = (tid >> 5) * 40 + (tid & 31);
    const size_t tok0 = (size_t)b * NT;

    // preload t = 0, 1 and stage bufs 0, 1
    float v0c = vc[tok0 * NC + vchan], a0c = ga[tok0 * NC + vchan];
    float be0 = gbeta[tok0 * NH + h];
    float v1c = vc[(tok0 + 1) * NC + vchan], a1c = ga[(tok0 + 1) * NC + vchan];
    float be1 = gbeta[(tok0 + 1) * NH + h];
    sk[0][sidx] = kc[tok0 * NC + kchan];
    sq[0][sidx] = qc[tok0 * NC + kchan];
    sk[1][sidx] = kc[(tok0 + 1) * NC + kchan];
    sq[1][sidx] = qc[(tok0 + 1) * NC + kchan];

    // per-step body (reads staged k/q from buf; v/a/beta from regs)
    auto step = [&](int buf, float v_cur, float a_cur, float be_cur, int t) {
        const float4* kb = (const float4*)&sk[buf][kq * 40];
        const float4* qb = (const float4*)&sq[buf][kq * 40];

        float p0 = 0.f, p1 = 0.f, p2 = 0.f, p3 = 0.f;
        float p4 = 0.f, p5 = 0.f, p6 = 0.f, p7 = 0.f;
#pragma unroll
        for (int j = 0; j < 4; j++) {
            const float4 ka  = kb[2 * j];
            const float4 kc2 = kb[2 * j + 1];
            p0 = fmaf(S[8*j+0], ka.x,  p0);
            p1 = fmaf(S[8*j+1], ka.y,  p1);
            p2 = fmaf(S[8*j+2], ka.z,  p2);
            p3 = fmaf(S[8*j+3], ka.w,  p3);
            p4 = fmaf(S[8*j+4], kc2.x, p4);
            p5 = fmaf(S[8*j+5], kc2.y, p5);
            p6 = fmaf(S[8*j+6], kc2.z, p6);
            p7 = fmaf(S[8*j+7], kc2.w, p7);
        }
        float Sk = ((p0 + p1) + (p2 + p3)) + ((p4 + p5) + (p6 + p7));
        Sk += __shfl_xor_sync(0xffffffffu, Sk, 1);
        Sk += __shfl_xor_sync(0xffffffffu, Sk, 2);

        const float coef = be_cur * (Sk - v_cur);
        const float a = a_cur;

        float o0 = 0.f, o1 = 0.f, o2 = 0.f, o3 = 0.f;
        float o4r = 0.f, o5 = 0.f, o6 = 0.f, o7 = 0.f;
#pragma unroll
        for (int j = 0; j < 4; j++) {
            const float4 ka  = kb[2 * j];
            const float4 kc2 = kb[2 * j + 1];
            const float4 qa  = qb[2 * j];
            const float4 qc2 = qb[2 * j + 1];
            S[8*j+0] = fmaf(a, S[8*j+0], -coef * ka.x);  o0  = fmaf(S[8*j+0], qa.x,  o0);
            S[8*j+1] = fmaf(a, S[8*j+1], -coef * ka.y);  o1  = fmaf(S[8*j+1], qa.y,  o1);
            S[8*j+2] = fmaf(a, S[8*j+2], -coef * ka.z);  o2  = fmaf(S[8*j+2], qa.z,  o2);
            S[8*j+3] = fmaf(a, S[8*j+3], -coef * ka.w);  o3  = fmaf(S[8*j+3], qa.w,  o3);
            S[8*j+4] = fmaf(a, S[8*j+4], -coef * kc2.x); o4r = fmaf(S[8*j+4], qc2.x, o4r);
            S[8*j+5] = fmaf(a, S[8*j+5], -coef * kc2.y); o5  = fmaf(S[8*j+5], qc2.y, o5);
            S[8*j+6] = fmaf(a, S[8*j+6], -coef * kc2.z); o6  = fmaf(S[8*j+6], qc2.z, o6);
            S[8*j+7] = fmaf(a, S[8*j+7], -coef * kc2.w); o7  = fmaf(S[8*j+7], qc2.w, o7);
        }
        const float op = ((o0 + o1) + (o2 + o3)) + ((o4r + o5) + (o6 + o7));
        o4[((tok0 + t) * NC + vchan) * 4 + kq] = op;
    };

    for (int t = 0; t < NT; t += 2) {
        __syncthreads();   // bufs t, t+1 visible; prev iteration's reads complete

        // prefetch t+2, t+3
        float k2 = 0.f, q2 = 0.f, v2 = 0.f, a2 = 0.f, be2 = 0.f;
        float k3 = 0.f, q3 = 0.f, v3 = 0.f, a3 = 0.f, be3 = 0.f;
        const bool more = (t + 2 < NT);
        if (more) {
            const size_t i2 = (tok0 + t + 2) * NC;
            const size_t i3 = (tok0 + t + 3) * NC;
            k2 = kc[i2 + kchan]; q2 = qc[i2 + kchan];
            v2 = vc[i2 + vchan]; a2 = ga[i2 + vchan];
            be2 = gbeta[(tok0 + t + 2) * NH + h];
            k3 = kc[i3 + kchan]; q3 = qc[i3 + kchan];
            v3 = vc[i3 + vchan]; a3 = ga[i3 + vchan];
            be3 = gbeta[(tok0 + t + 3) * NH + h];
        }

        step(t & 3,       v0c, a0c, be0, t);
        step((t + 1) & 3, v1c, a1c, be1, t + 1);

        if (more) {
            sk[(t + 2) & 3][sidx] = k2; sq[(t + 2) & 3][sidx] = q2;
            sk[(t + 3) & 3][sidx] = k3; sq[(t + 3) & 3][sidx] = q3;
        }
        v0c = v2; a0c = a2; be0 = be2;
        v1c = v3; a1c = a3; be1 = be3;
    }
}

// ------------------------------------------------------------------
// Sum 4 partials + LayerNorm + gate + bf16 split directly into g_xs.
// ------------------------------------------------------------------
__global__ void __launch_bounds__(128)
ln_gate_split(const float* __restrict__ o4, const float* __restrict__ gg,
              const float* __restrict__ ln_g, const float* __restrict__ ln_b,
              __nv_bfloat16* __restrict__ xs)
{
    const int bid = blockIdx.x;
    const int tok = bid >> 4, h = bid & 15;
    const int v = threadIdx.x, lane = v & 31, wid = v >> 5;
    const int chan = h * NDK + v;
    const size_t idx = (size_t)tok * NC + chan;

    const float4 part = ((const float4*)o4)[idx];
    const float o = (part.x + part.y) + (part.z + part.w);

    __shared__ float red[8];
    float rs = o, rs2 = o * o;
#pragma unroll
    for (int off = 16; off > 0; off >>= 1) {
        rs  += __shfl_xor_sync(0xffffffffu, rs,  off);
        rs2 += __shfl_xor_sync(0xffffffffu, rs2, off);
    }
    if (lane == 0) { red[wid] = rs; red[4 + wid] = rs2; }
    __syncthreads();
    const float mu  = (red[0] + red[1] + red[2] + red[3]) * (1.f / 128.f);
    const float ms  = (red[4] + red[5] + red[6] + red[7]) * (1.f / 128.f);
    const float var = ms - mu * mu;
    const float y = ((o - mu) * rsqrtf(var + 1e-5f) * ln_g[v] + ln_b[v]) * gg[idx];

    const __nv_bfloat16 hbf = __float2bfloat16(y);
    const __nv_bfloat16 lbf = __float2bfloat16(y - __bfloat162float(hbf));
    __nv_bfloat16* base = xs + (size_t)tok * KS + chan;
    base[0]    = hbf;
    base[2048] = lbf;
    base[4096] = hbf;
}

// ------------------------------------------------------------------
// Launch
// ------------------------------------------------------------------
extern "C" void kernel_launch(void* const* d_in, const int* in_sizes, int n_in,
                              void* d_out, int out_size)
{
    const float* x        = (const float*)d_in[0];
    const float* Wq       = (const float*)d_in[1];
    const float* Wk       = (const float*)d_in[2];
    const float* Wv       = (const float*)d_in[3];
    const float* Wa       = (const float*)d_in[4];
    const float* ba       = (const float*)d_in[5];
    const float* Wb       = (const float*)d_in[6];
    const float* bb       = (const float*)d_in[7];
    const float* conv_q_w = (const float*)d_in[8];
    const float* conv_q_b = (const float*)d_in[9];
    const float* conv_k_w = (const float*)d_in[10];
    const float* conv_k_b = (const float*)d_in[11];
    const float* conv_v_w = (const float*)d_in[12];
    const float* conv_v_b = (const float*)d_in[13];
    const float* Wg       = (const float*)d_in[14];
    const float* ln_g     = (const float*)d_in[15];
    const float* ln_b     = (const float*)d_in[16];
    const float* Wo       = (const float*)d_in[17];
    float* out = (float*)d_out;

    __nv_bfloat16 *xs, *ws;
    float *q0, *k0, *v0, *qc, *kc, *vc, *pa, *pg, *po4, *pbeta;
    cudaGetSymbolAddress((void**)&xs,    g_xs);
    cudaGetSymbolAddress((void**)&ws,    g_ws);
    cudaGetSymbolAddress((void**)&q0,    g_q0);
    cudaGetSymbolAddress((void**)&k0,    g_k0);
    cudaGetSymbolAddress((void**)&v0,    g_v0);
    cudaGetSymbolAddress((void**)&qc,    g_qc);
    cudaGetSymbolAddress((void**)&kc,    g_kc);
    cudaGetSymbolAddress((void**)&vc,    g_vc);
    cudaGetSymbolAddress((void**)&pa,    g_a);
    cudaGetSymbolAddress((void**)&pg,    g_gt);
    cudaGetSymbolAddress((void**)&po4,   g_o4);
    cudaGetSymbolAddress((void**)&pbeta, g_bt);

    static bool attr_set = false;
    if (!attr_set) {
        cudaFuncSetAttribute(tgemm, cudaFuncAttributeMaxDynamicSharedMemorySize, TG_SMEM);
        attr_set = true;
    }

    const int q4blk = ((NTOK * ND) / 4 + 255) / 256;       // 4096
    const int c2blk = ((NTOK / 2) * (NC / 4) + 255) / 256; // 2048

    // all splits (x + 6 weights) in one launch; beta from fp32 x
    split_all<<<dim3(q4blk, 7), 256>>>(x, Wq, Wk, Wv, Wa, Wg, Wo, xs, ws);
    beta_k<<<NTOK, 256>>>(x, Wb, bb, pbeta);

    // fused 5-projection GEMM (q, k, v, a, g) — N = 10240
    tgemm<<<dim3(80, 16), 256, TG_SMEM>>>(xs, ws, ba, q0, k0, v0, pa, pg);

    // fused conv + silu (q, k*DK^-0.5, v), 2 tokens per thread
    conv3<<<dim3(c2blk, 3), 256>>>(q0, k0, v0, conv_q_w, conv_k_w, conv_v_w,
                                   conv_q_b, conv_k_b, conv_v_b, qc, kc, vc);

    // recurrence (v-split 4x, 4-buffer staging) then LN + gate + split into xs
    recur2<<<NB * NH * 4, 128>>>(qc, kc, vc, pa, pbeta, po4);
    ln_gate_split<<<NTOK * NH, 128>>>(po4, pg, ln_g, ln_b, xs);

    // output projection (seg = 0 -> plain store to out)
    tgemm<<<dim3(16, 16), 256, TG_SMEM>>>(xs, ws + 5 * WSTRIDE, nullptr,
                                          out, out, out, out, out);
}

// round 9
// speedup vs baseline: 1.2041x; 1.0356x over previous
#include <cuda_runtime.h>
#include <cuda_bf16.h>
#include <math.h>
#include <stdint.h>

#define NB   2
#define NT   1024
#define ND   2048
#define NH   16
#define NDK  128
#define NTOK (NB*NT)      /* 2048 tokens */
#define NC   (NH*NDK)     /* 2048 channels */
#define KS   (3*ND)       /* 6144: split-precision K (hi|lo|hi) */
#define WSTRIDE ((size_t)NC*KS)

// ------------------------------------------------------------------
// Scratch (device globals; no runtime allocation allowed)
// ------------------------------------------------------------------
__device__ __nv_bfloat16 g_xs[(size_t)NTOK*KS];   // split activations
__device__ __nv_bfloat16 g_ws[6*WSTRIDE];         // 6 split weights (q,k,v,a,g,o)
__device__ float g_q0[NTOK*NC];
__device__ float g_k0[NTOK*NC];
__device__ float g_v0[NTOK*NC];
__device__ float g_qc[NTOK*NC];
__device__ float g_kc[NTOK*NC];
__device__ float g_vc[NTOK*NC];
__device__ float g_a [NTOK*NC];
__device__ float g_gt[NTOK*NC];
__device__ float g_o4[(size_t)NTOK*NC*4];         // 4 partial recurrence outputs / channel
__device__ float g_bt[NTOK*NH];

// ==================================================================
// Helpers
// ==================================================================
__device__ __forceinline__ uint32_t smem_u32(const void* p) {
    uint32_t r;
    asm("{ .reg .u64 t; cvta.to.shared.u64 t, %1; cvt.u32.u64 %0, t; }"
        : "=r"(r) : "l"(p));
    return r;
}
__device__ __forceinline__ void cp16(uint32_t dst, const void* src) {
    asm volatile("cp.async.cg.shared.global [%0], [%1], 16;\n" :: "r"(dst), "l"(src));
}
__device__ __forceinline__ void cp_commit() {
    asm volatile("cp.async.commit_group;\n" ::: "memory");
}
__device__ __forceinline__ void cp_wait1() {
    asm volatile("cp.async.wait_group 1;\n" ::: "memory");
}
__device__ __forceinline__ void cp_wait0() {
    asm volatile("cp.async.wait_group 0;\n" ::: "memory");
}
__device__ __forceinline__ void ldsm4(uint32_t& r0, uint32_t& r1, uint32_t& r2,
                                      uint32_t& r3, uint32_t addr) {
    asm volatile("ldmatrix.sync.aligned.m8n8.x4.shared.b16 {%0,%1,%2,%3}, [%4];"
                 : "=r"(r0), "=r"(r1), "=r"(r2), "=r"(r3) : "r"(addr));
}
__device__ __forceinline__ void mma16816(float* d, const uint32_t* a,
                                         uint32_t b0, uint32_t b1) {
    asm volatile(
        "mma.sync.aligned.m16n8k16.row.col.f32.bf16.bf16.f32 "
        "{%0,%1,%2,%3}, {%4,%5,%6,%7}, {%8,%9}, {%0,%1,%2,%3};"
        : "+f"(d[0]), "+f"(d[1]), "+f"(d[2]), "+f"(d[3])
        : "r"(a[0]), "r"(a[1]), "r"(a[2]), "r"(a[3]), "r"(b0), "r"(b1));
}
__device__ __forceinline__ float fsig(float z) {
    return 1.f / (1.f + __expf(-z));
}

// ==================================================================
// Tensor-core GEMM (HMMA): fused 5-projection (grid.x=80) or Wo (grid.x=16)
// 128x128 tile, BK=64, 3-stage cp.async pipeline (96 KB smem), 8 warps.
// (R5 configuration — verbatim; known-good local optimum.)
// ==================================================================
#define BK      64
#define KITERS  (KS/BK)      /* 96 */
#define STG_B   32768
#define STAGES  3
#define TG_SMEM (STAGES*STG_B)

__global__ void __launch_bounds__(256, 2)
tgemm(const __nv_bfloat16* __restrict__ A, const __nv_bfloat16* __restrict__ Bw,
      const float* __restrict__ bias_a,
      float* __restrict__ Cq, float* __restrict__ Ck, float* __restrict__ Cv,
      float* __restrict__ Ca, float* __restrict__ Cg)
{
    extern __shared__ __align__(1024) char smem[];
    const uint32_t sb = smem_u32(smem);

    const int tid  = threadIdx.x;
    const int lane = tid & 31;
    const int wid  = tid >> 5;
    const int wm   = wid & 3;
    const int wn   = wid >> 2;
    const int m0   = blockIdx.y * 128;
    const int n0g  = blockIdx.x * 128;
    const int seg  = blockIdx.x >> 4;
    const int col0 = (blockIdx.x & 15) * 128;

    const int r0 = tid >> 3;
    const int c0 = tid & 7;
    const uint32_t stOff = (uint32_t)(((c0 ^ (r0 & 7)) << 4));

    const __nv_bfloat16* gA = A  + (size_t)(m0  + r0) * KS + c0 * 8;
    const __nv_bfloat16* gB = Bw + (size_t)(n0g + r0) * KS + c0 * 8;

    const int la = lane & 15, ha = lane >> 4;
    const int arow = wm * 32 + la;
    const uint32_t aswz = arow & 7;
    const int brow = wn * 64 + (lane & 7) + ((lane >> 4) & 1) * 8;
    const uint32_t bswz = brow & 7;
    const uint32_t bsel = (lane >> 3) & 1;

    uint32_t aoff[4], boff[4];
#pragma unroll
    for (int kh = 0; kh < 4; kh++) {
        aoff[kh] = arow * 128 + (((uint32_t)((2 * kh + ha) ^ aswz)) << 4);
        boff[kh] = 16384 + brow * 128 + (((uint32_t)((2 * kh + bsel) ^ bswz)) << 4);
    }

    float acc[2][8][4];
#pragma unroll
    for (int mi = 0; mi < 2; mi++)
#pragma unroll
        for (int ni = 0; ni < 8; ni++)
#pragma unroll
            for (int e = 0; e < 4; e++) acc[mi][ni][e] = 0.f;

#pragma unroll
    for (int s = 0; s < STAGES - 1; s++) {
        const uint32_t base = sb + s * STG_B;
        const int kc = s * BK;
#pragma unroll
        for (int r = 0; r < 4; r++) {
            const uint32_t so = (r0 + 32 * r) * 128 + stOff;
            cp16(base + so,         gA + (size_t)(32 * r) * KS + kc);
            cp16(base + 16384 + so, gB + (size_t)(32 * r) * KS + kc);
        }
        cp_commit();
    }

    int stage = 0;
    for (int it = 0; it < KITERS; it++) {
        if (it < KITERS - 1) cp_wait1(); else cp_wait0();
        __syncthreads();

        if (it + 2 < KITERS) {
            const int ps = (stage + 2 >= STAGES) ? stage + 2 - STAGES : stage + 2;
            const uint32_t base = sb + ps * STG_B;
            const int kc = (it + 2) * BK;
#pragma unroll
            for (int r = 0; r < 4; r++) {
                const uint32_t so = (r0 + 32 * r) * 128 + stOff;
                cp16(base + so,         gA + (size_t)(32 * r) * KS + kc);
                cp16(base + 16384 + so, gB + (size_t)(32 * r) * KS + kc);
            }
        }
        cp_commit();

        const uint32_t base = sb + stage * STG_B;
        stage = (stage + 1 >= STAGES) ? 0 : stage + 1;

#pragma unroll
        for (int kh = 0; kh < 4; kh++) {
            uint32_t av[2][4];
            ldsm4(av[0][0], av[0][1], av[0][2], av[0][3], base + aoff[kh]);
            ldsm4(av[1][0], av[1][1], av[1][2], av[1][3], base + aoff[kh] + 2048);

            uint32_t bv[4][4];
#pragma unroll
            for (int p = 0; p < 4; p++)
                ldsm4(bv[p][0], bv[p][1], bv[p][2], bv[p][3],
                      base + boff[kh] + p * 2048);

#pragma unroll
            for (int mi = 0; mi < 2; mi++)
#pragma unroll
                for (int ni = 0; ni < 8; ni++) {
                    const int p = ni >> 1;
                    const int h = (ni & 1) * 2;
                    mma16816(acc[mi][ni], av[mi], bv[p][h], bv[p][h + 1]);
                }
        }
    }

    float* C = (seg == 0) ? Cq : (seg == 1) ? Ck : (seg == 2) ? Cv
             : (seg == 3) ? Ca : Cg;
    const int et = (seg == 3) ? 1 : (seg == 4) ? 2 : 0;

    const int g  = lane >> 2;
    const int tg = lane & 3;
#pragma unroll
    for (int mi = 0; mi < 2; mi++) {
        const int row = m0 + wm * 32 + mi * 16 + g;
#pragma unroll
        for (int ni = 0; ni < 8; ni++) {
            const int col = col0 + wn * 64 + ni * 8 + tg * 2;
            float v0 = acc[mi][ni][0], v1 = acc[mi][ni][1];
            float v2 = acc[mi][ni][2], v3 = acc[mi][ni][3];
            if (et == 1) {
                const float b0 = bias_a[col], b1 = bias_a[col + 1];
                v0 = fsig(v0 + b0); v1 = fsig(v1 + b1);
                v2 = fsig(v2 + b0); v3 = fsig(v3 + b1);
            } else if (et == 2) {
                v0 = fsig(v0); v1 = fsig(v1); v2 = fsig(v2); v3 = fsig(v3);
            }
            *(float2*)(C + (size_t)row * NC + col)       = make_float2(v0, v1);
            *(float2*)(C + (size_t)(row + 8) * NC + col) = make_float2(v2, v3);
        }
    }
}

// ------------------------------------------------------------------
// Split fp32 -> bf16 hi/lo, K-concatenated (float4 vectorized).
// ------------------------------------------------------------------
__device__ __forceinline__ void split_body(const float* __restrict__ in,
                                           __nv_bfloat16* __restrict__ out,
                                           int mode, int i)
{
    const int r  = i >> 9;
    const int k4 = (i << 2) & 2047;
    const float4 a = ((const float4*)in)[i];

    __nv_bfloat162 h01 = __floats2bfloat162_rn(a.x, a.y);
    __nv_bfloat162 h23 = __floats2bfloat162_rn(a.z, a.w);
    const float lx = a.x - __bfloat162float(__low2bfloat16(h01));
    const float ly = a.y - __bfloat162float(__high2bfloat16(h01));
    const float lz = a.z - __bfloat162float(__low2bfloat16(h23));
    const float lw = a.w - __bfloat162float(__high2bfloat16(h23));
    __nv_bfloat162 l01 = __floats2bfloat162_rn(lx, ly);
    __nv_bfloat162 l23 = __floats2bfloat162_rn(lz, lw);

    uint2 hp, lp;
    hp.x = *(const uint32_t*)&h01; hp.y = *(const uint32_t*)&h23;
    lp.x = *(const uint32_t*)&l01; lp.y = *(const uint32_t*)&l23;

    __nv_bfloat16* base = out + (size_t)r * KS + k4;
    *(uint2*)(base) = hp;
    if (mode == 0) { *(uint2*)(base + 2048) = lp; *(uint2*)(base + 4096) = hp; }
    else           { *(uint2*)(base + 2048) = hp; *(uint2*)(base + 4096) = lp; }
}

__global__ void __launch_bounds__(256)
split_all(const float* __restrict__ x,  const float* __restrict__ Wq,
          const float* __restrict__ Wk, const float* __restrict__ Wv,
          const float* __restrict__ Wa, const float* __restrict__ Wg,
          const float* __restrict__ Wo,
          __nv_bfloat16* __restrict__ xs, __nv_bfloat16* __restrict__ ws)
{
    const int i = blockIdx.x * 256 + threadIdx.x;
    if (i >= (NTOK * ND) / 4) return;
    const int which = blockIdx.y;
    if (which == 0)      split_body(x,  xs, 0, i);
    else if (which == 1) split_body(Wq, ws + 0 * WSTRIDE, 1, i);
    else if (which == 2) split_body(Wk, ws + 1 * WSTRIDE, 1, i);
    else if (which == 3) split_body(Wv, ws + 2 * WSTRIDE, 1, i);
    else if (which == 4) split_body(Wa, ws + 3 * WSTRIDE, 1, i);
    else if (which == 5) split_body(Wg, ws + 4 * WSTRIDE, 1, i);
    else                 split_body(Wo, ws + 5 * WSTRIDE, 1, i);
}

// ------------------------------------------------------------------
// beta = sigmoid(x @ Wb^T + bb)
// ------------------------------------------------------------------
__global__ void __launch_bounds__(256)
beta_k(const float* __restrict__ x, const float* __restrict__ Wb,
       const float* __restrict__ bb, float* __restrict__ out)
{
    __shared__ float xs[ND];
    const int row = blockIdx.x;
    for (int i = threadIdx.x; i < ND; i += 256) xs[i] = x[(size_t)row * ND + i];
    __syncthreads();
    const int w = threadIdx.x >> 5, lane = threadIdx.x & 31;
    for (int h = w; h < NH; h += 8) {
        const float* wr = Wb + (size_t)h * ND;
        float s = 0.f;
        for (int i = lane; i < ND; i += 32) s = fmaf(xs[i], wr[i], s);
#pragma unroll
        for (int o = 16; o > 0; o >>= 1) s += __shfl_xor_sync(0xffffffffu, s, o);
        if (lane == 0) out[(size_t)row * NH + h] = fsig(s + bb[h]);
    }
}

// ------------------------------------------------------------------
// Fused causal depthwise conv (K=4) + bias + silu + scale.
// 2 consecutive tokens per thread (5 row-loads -> 2 outputs).
// ------------------------------------------------------------------
__global__ void __launch_bounds__(256)
conv3(const float* __restrict__ q0, const float* __restrict__ k0,
      const float* __restrict__ v0,
      const float* __restrict__ wq, const float* __restrict__ wk,
      const float* __restrict__ wv,
      const float* __restrict__ bq, const float* __restrict__ bk,
      const float* __restrict__ bv,
      float* __restrict__ qc, float* __restrict__ kc, float* __restrict__ vc)
{
    const int i = blockIdx.x * 256 + threadIdx.x;
    if (i >= (NTOK / 2) * (NC / 4)) return;

    const float* in; const float* w; const float* bias; float* out; float scale;
    if (blockIdx.y == 0)      { in = q0; w = wq; bias = bq; out = qc; scale = 1.f; }
    else if (blockIdx.y == 1) { in = k0; w = wk; bias = bk; out = kc; scale = 0.08838834764831845f; }
    else                      { in = v0; w = wv; bias = bv; out = vc; scale = 1.f; }

    const int cg   = i & (NC / 4 - 1);
    const int pair = i >> 9;
    const int c    = cg * 4;
    const int t0   = (pair & (NT / 2 - 1)) * 2;
    const int b    = pair >> 9;

    const float4 w0 = ((const float4*)w)[c + 0];
    const float4 w1 = ((const float4*)w)[c + 1];
    const float4 w2 = ((const float4*)w)[c + 2];
    const float4 w3 = ((const float4*)w)[c + 3];
    const float4 bi = *(const float4*)(bias + c);

    const float* p = in + ((size_t)b * NT + t0) * NC + c;
    const float4 z = make_float4(0.f, 0.f, 0.f, 0.f);
    const float4 xm3 = (t0 >= 3) ? *(const float4*)(p - 3 * NC) : z;
    const float4 xm2 = (t0 >= 2) ? *(const float4*)(p - 2 * NC) : z;
    const float4 xm1 = (t0 >= 1) ? *(const float4*)(p - NC)     : z;
    const float4 x0  = *(const float4*)p;
    const float4 xp1 = *(const float4*)(p + NC);

    float4 a0 = bi;
    a0.x = fmaf(w0.x, xm3.x, a0.x); a0.y = fmaf(w1.x, xm3.y, a0.y);
    a0.z = fmaf(w2.x, xm3.z, a0.z); a0.w = fmaf(w3.x, xm3.w, a0.w);
    a0.x = fmaf(w0.y, xm2.x, a0.x); a0.y = fmaf(w1.y, xm2.y, a0.y);
    a0.z = fmaf(w2.y, xm2.z, a0.z); a0.w = fmaf(w3.y, xm2.w, a0.w);
    a0.x = fmaf(w0.z, xm1.x, a0.x); a0.y = fmaf(w1.z, xm1.y, a0.y);
    a0.z = fmaf(w2.z, xm1.z, a0.z); a0.w = fmaf(w3.z, xm1.w, a0.w);
    a0.x = fmaf(w0.w, x0.x,  a0.x); a0.y = fmaf(w1.w, x0.y,  a0.y);
    a0.z = fmaf(w2.w, x0.z,  a0.z); a0.w = fmaf(w3.w, x0.w,  a0.w);

    float4 a1 = bi;
    a1.x = fmaf(w0.x, xm2.x, a1.x); a1.y = fmaf(w1.x, xm2.y, a1.y);
    a1.z = fmaf(w2.x, xm2.z, a1.z); a1.w = fmaf(w3.x, xm2.w, a1.w);
    a1.x = fmaf(w0.y, xm1.x, a1.x); a1.y = fmaf(w1.y, xm1.y, a1.y);
    a1.z = fmaf(w2.y, xm1.z, a1.z); a1.w = fmaf(w3.y, xm1.w, a1.w);
    a1.x = fmaf(w0.z, x0.x,  a1.x); a1.y = fmaf(w1.z, x0.y,  a1.y);
    a1.z = fmaf(w2.z, x0.z,  a1.z); a1.w = fmaf(w3.z, x0.w,  a1.w);
    a1.x = fmaf(w0.w, xp1.x, a1.x); a1.y = fmaf(w1.w, xp1.y, a1.y);
    a1.z = fmaf(w2.w, xp1.z, a1.z); a1.w = fmaf(w3.w, xp1.w, a1.w);

    float4 r0o, r1o;
    r0o.x = a0.x * fsig(a0.x) * scale; r0o.y = a0.y * fsig(a0.y) * scale;
    r0o.z = a0.z * fsig(a0.z) * scale; r0o.w = a0.w * fsig(a0.w) * scale;
    r1o.x = a1.x * fsig(a1.x) * scale; r1o.y = a1.y * fsig(a1.y) * scale;
    r1o.z = a1.z * fsig(a1.z) * scale; r1o.w = a1.w * fsig(a1.w) * scale;

    float* po = out + ((size_t)b * NT + t0) * NC + c;
    *(float4*)po        = r0o;
    *(float4*)(po + NC) = r1o;
}

// ------------------------------------------------------------------
// Recurrence, v-split 4x, 8-buffer staging (prefetch distance 4),
// one __syncthreads per 2 steps, PIPELINED Sk:
//   Sk(t+1) = S_after(t) . k(t+1) accumulated inside the update loop.
// Thread (vloc = tid>>2, kq = tid&3) owns S[vloc][kq*32 .. +31].
// ------------------------------------------------------------------
__global__ void __launch_bounds__(128)
recur2(const float* __restrict__ qc, const float* __restrict__ kc,
       const float* __restrict__ vc, const float* __restrict__ ga,
       const float* __restrict__ gbeta, float* __restrict__ o4)
{
    const int bid  = blockIdx.x;
    const int b    = bid >> 6;
    const int h    = (bid >> 2) & 15;
    const int vblk = bid & 3;
    const int tid  = threadIdx.x;
    const int vloc = tid >> 2;
    const int kq   = tid & 3;

    __shared__ __align__(16) float sk[8][160];
    __shared__ __align__(16) float sq[8][160];

    float S[32];
#pragma unroll
    for (int j = 0; j < 32; j++) S[j] = 0.f;

    const int kchan = h * NDK + tid;
    const int vchan = h * NDK + vblk * 32 + vloc;
    const int sidx  = (tid >> 5) * 40 + (tid & 31);
    const size_t tok0 = (size_t)b * NT;

    // prologue: stage bufs 0..3; preload v/a/beta for t = 0..3
#pragma unroll
    for (int tt = 0; tt < 4; tt++) {
        sk[tt][sidx] = kc[(tok0 + tt) * NC + kchan];
        sq[tt][sidx] = qc[(tok0 + tt) * NC + kchan];
    }
    float v0c = vc[(tok0 + 0) * NC + vchan], a0c = ga[(tok0 + 0) * NC + vchan];
    float v1c = vc[(tok0 + 1) * NC + vchan], a1c = ga[(tok0 + 1) * NC + vchan];
    float v2c = vc[(tok0 + 2) * NC + vchan], a2c = ga[(tok0 + 2) * NC + vchan];
    float v3c = vc[(tok0 + 3) * NC + vchan], a3c = ga[(tok0 + 3) * NC + vchan];
    float be0 = gbeta[(tok0 + 0) * NH + h];
    float be1 = gbeta[(tok0 + 1) * NH + h];
    float be2 = gbeta[(tok0 + 2) * NH + h];
    float be3 = gbeta[(tok0 + 3) * NH + h];

    float Skr = 0.f;   // reduced S.k for the CURRENT step (S_init = 0)

    auto step = [&](int buf, int nbuf, float v_cur, float a_cur, float be_cur, int t) {
        const float4* kb = (const float4*)&sk[buf][kq * 40];
        const float4* qb = (const float4*)&sq[buf][kq * 40];
        const float4* kn = (const float4*)&sk[nbuf][kq * 40];

        const float coef = be_cur * (Skr - v_cur);
        const float a = a_cur;

        float o0 = 0.f, o1 = 0.f, o2 = 0.f, o3 = 0.f;
        float o4r = 0.f, o5 = 0.f, o6 = 0.f, o7 = 0.f;
        float s0 = 0.f, s1 = 0.f, s2 = 0.f, s3 = 0.f;
        float s4 = 0.f, s5 = 0.f, s6 = 0.f, s7 = 0.f;
#pragma unroll
        for (int j = 0; j < 4; j++) {
            const float4 ka  = kb[2 * j];
            const float4 kc2 = kb[2 * j + 1];
            const float4 qa  = qb[2 * j];
            const float4 qc2 = qb[2 * j + 1];
            const float4 na  = kn[2 * j];
            const float4 nc2 = kn[2 * j + 1];
            S[8*j+0] = fmaf(a, S[8*j+0], -coef * ka.x);
            o0 = fmaf(S[8*j+0], qa.x,  o0);  s0 = fmaf(S[8*j+0], na.x,  s0);
            S[8*j+1] = fmaf(a, S[8*j+1], -coef * ka.y);
            o1 = fmaf(S[8*j+1], qa.y,  o1);  s1 = fmaf(S[8*j+1], na.y,  s1);
            S[8*j+2] = fmaf(a, S[8*j+2], -coef * ka.z);
            o2 = fmaf(S[8*j+2], qa.z,  o2);  s2 = fmaf(S[8*j+2], na.z,  s2);
            S[8*j+3] = fmaf(a, S[8*j+3], -coef * ka.w);
            o3 = fmaf(S[8*j+3], qa.w,  o3);  s3 = fmaf(S[8*j+3], na.w,  s3);
            S[8*j+4] = fmaf(a, S[8*j+4], -coef * kc2.x);
            o4r = fmaf(S[8*j+4], qc2.x, o4r); s4 = fmaf(S[8*j+4], nc2.x, s4);
            S[8*j+5] = fmaf(a, S[8*j+5], -coef * kc2.y);
            o5 = fmaf(S[8*j+5], qc2.y, o5);  s5 = fmaf(S[8*j+5], nc2.y, s5);
            S[8*j+6] = fmaf(a, S[8*j+6], -coef * kc2.z);
            o6 = fmaf(S[8*j+6], qc2.z, o6);  s6 = fmaf(S[8*j+6], nc2.z, s6);
            S[8*j+7] = fmaf(a, S[8*j+7], -coef * kc2.w);
            o7 = fmaf(S[8*j+7], qc2.w, o7);  s7 = fmaf(S[8*j+7], nc2.w, s7);
        }
        float skn = ((s0 + s1) + (s2 + s3)) + ((s4 + s5) + (s6 + s7));
        skn += __shfl_xor_sync(0xffffffffu, skn, 1);
        skn += __shfl_xor_sync(0xffffffffu, skn, 2);

        const float op = ((o0 + o1) + (o2 + o3)) + ((o4r + o5) + (o6 + o7));
        o4[((tok0 + t) * NC + vchan) * 4 + kq] = op;

        Skr = skn;
    };

    for (int t = 0; t < NT; t += 2) {
        __syncthreads();   // bufs t..t+3 staged & visible; prior reads complete

        // prefetch t+4, t+5 (regs)
        float k4 = 0.f, q4 = 0.f, v4 = 0.f, a4 = 0.f, be4 = 0.f;
        float k5 = 0.f, q5 = 0.f, v5 = 0.f, a5 = 0.f, be5 = 0.f;
        const bool more = (t + 4 < NT);
        if (more) {
            const size_t i4 = (tok0 + t + 4) * NC;
            const size_t i5 = (tok0 + t + 5) * NC;
            k4 = kc[i4 + kchan]; q4 = qc[i4 + kchan];
            v4 = vc[i4 + vchan]; a4 = ga[i4 + vchan];
            be4 = gbeta[(tok0 + t + 4) * NH + h];
            k5 = kc[i5 + kchan]; q5 = qc[i5 + kchan];
            v5 = vc[i5 + vchan]; a5 = ga[i5 + vchan];
            be5 = gbeta[(tok0 + t + 5) * NH + h];
        }

        step(t & 7,       (t + 1) & 7, v0c, a0c, be0, t);
        step((t + 1) & 7, (t + 2) & 7, v1c, a1c, be1, t + 1);

        if (more) {
            sk[(t + 4) & 7][sidx] = k4; sq[(t + 4) & 7][sidx] = q4;
            sk[(t + 5) & 7][sidx] = k5; sq[(t + 5) & 7][sidx] = q5;
        }
        v0c = v2c; a0c = a2c; be0 = be2;
        v1c = v3c; a1c = a3c; be1 = be3;
        v2c = v4;  a2c = a4;  be2 = be4;
        v3c = v5;  a3c = a5;  be3 = be5;
    }
}

// ------------------------------------------------------------------
// Sum 4 partials + LayerNorm + gate + bf16 split directly into g_xs.
// ------------------------------------------------------------------
__global__ void __launch_bounds__(128)
ln_gate_split(const float* __restrict__ o4, const float* __restrict__ gg,
              const float* __restrict__ ln_g, const float* __restrict__ ln_b,
              __nv_bfloat16* __restrict__ xs)
{
    const int bid = blockIdx.x;
    const int tok = bid >> 4, h = bid & 15;
    const int v = threadIdx.x, lane = v & 31, wid = v >> 5;
    const int chan = h * NDK + v;
    const size_t idx = (size_t)tok * NC + chan;

    const float4 part = ((const float4*)o4)[idx];
    const float o = (part.x + part.y) + (part.z + part.w);

    __shared__ float red[8];
    float rs = o, rs2 = o * o;
#pragma unroll
    for (int off = 16; off > 0; off >>= 1) {
        rs  += __shfl_xor_sync(0xffffffffu, rs,  off);
        rs2 += __shfl_xor_sync(0xffffffffu, rs2, off);
    }
    if (lane == 0) { red[wid] = rs; red[4 + wid] = rs2; }
    __syncthreads();
    const float mu  = (red[0] + red[1] + red[2] + red[3]) * (1.f / 128.f);
    const float ms  = (red[4] + red[5] + red[6] + red[7]) * (1.f / 128.f);
    const float var = ms - mu * mu;
    const float y = ((o - mu) * rsqrtf(var + 1e-5f) * ln_g[v] + ln_b[v]) * gg[idx];

    const __nv_bfloat16 hbf = __float2bfloat16(y);
    const __nv_bfloat16 lbf = __float2bfloat16(y - __bfloat162float(hbf));
    __nv_bfloat16* base = xs + (size_t)tok * KS + chan;
    base[0]    = hbf;
    base[2048] = lbf;
    base[4096] = hbf;
}

// ------------------------------------------------------------------
// Launch
// ------------------------------------------------------------------
extern "C" void kernel_launch(void* const* d_in, const int* in_sizes, int n_in,
                              void* d_out, int out_size)
{
    const float* x        = (const float*)d_in[0];
    const float* Wq       = (const float*)d_in[1];
    const float* Wk       = (const float*)d_in[2];
    const float* Wv       = (const float*)d_in[3];
    const float* Wa       = (const float*)d_in[4];
    const float* ba       = (const float*)d_in[5];
    const float* Wb       = (const float*)d_in[6];
    const float* bb       = (const float*)d_in[7];
    const float* conv_q_w = (const float*)d_in[8];
    const float* conv_q_b = (const float*)d_in[9];
    const float* conv_k_w = (const float*)d_in[10];
    const float* conv_k_b = (const float*)d_in[11];
    const float* conv_v_w = (const float*)d_in[12];
    const float* conv_v_b = (const float*)d_in[13];
    const float* Wg       = (const float*)d_in[14];
    const float* ln_g     = (const float*)d_in[15];
    const float* ln_b     = (const float*)d_in[16];
    const float* Wo       = (const float*)d_in[17];
    float* out = (float*)d_out;

    __nv_bfloat16 *xs, *ws;
    float *q0, *k0, *v0, *qc, *kc, *vc, *pa, *pg, *po4, *pbeta;
    cudaGetSymbolAddress((void**)&xs,    g_xs);
    cudaGetSymbolAddress((void**)&ws,    g_ws);
    cudaGetSymbolAddress((void**)&q0,    g_q0);
    cudaGetSymbolAddress((void**)&k0,    g_k0);
    cudaGetSymbolAddress((void**)&v0,    g_v0);
    cudaGetSymbolAddress((void**)&qc,    g_qc);
    cudaGetSymbolAddress((void**)&kc,    g_kc);
    cudaGetSymbolAddress((void**)&vc,    g_vc);
    cudaGetSymbolAddress((void**)&pa,    g_a);
    cudaGetSymbolAddress((void**)&pg,    g_gt);
    cudaGetSymbolAddress((void**)&po4,   g_o4);
    cudaGetSymbolAddress((void**)&pbeta, g_bt);

    static bool attr_set = false;
    if (!attr_set) {
        cudaFuncSetAttribute(tgemm, cudaFuncAttributeMaxDynamicSharedMemorySize, TG_SMEM);
        attr_set = true;
    }

    const int q4blk = ((NTOK * ND) / 4 + 255) / 256;       // 4096
    const int c2blk = ((NTOK / 2) * (NC / 4) + 255) / 256; // 2048

    // all splits (x + 6 weights) in one launch; beta from fp32 x
    split_all<<<dim3(q4blk, 7), 256>>>(x, Wq, Wk, Wv, Wa, Wg, Wo, xs, ws);
    beta_k<<<NTOK, 256>>>(x, Wb, bb, pbeta);

    // fused 5-projection GEMM (q, k, v, a, g) — N = 10240
    tgemm<<<dim3(80, 16), 256, TG_SMEM>>>(xs, ws, ba, q0, k0, v0, pa, pg);

    // fused conv + silu (q, k*DK^-0.5, v), 2 tokens per thread
    conv3<<<dim3(c2blk, 3), 256>>>(q0, k0, v0, conv_q_w, conv_k_w, conv_v_w,
                                   conv_q_b, conv_k_b, conv_v_b, qc, kc, vc);

    // recurrence (v-split 4x, pipelined Sk) then LN + gate + split into xs
    recur2<<<NB * NH * 4, 128>>>(qc, kc, vc, pa, pbeta, po4);
    ln_gate_split<<<NTOK * NH, 128>>>(po4, pg, ln_g, ln_b, xs);

    // output projection (seg = 0 -> plain store to out)
    tgemm<<<dim3(16, 16), 256, TG_SMEM>>>(xs, ws + 5 * WSTRIDE, nullptr,
                                          out, out, out, out, out);
}

// round 10
// speedup vs baseline: 1.2571x; 1.0440x over previous
#include <cuda_runtime.h>
#include <cuda_bf16.h>
#include <math.h>
#include <stdint.h>

#define NB   2
#define NT   1024
#define ND   2048
#define NH   16
#define NDK  128
#define NTOK (NB*NT)      /* 2048 tokens */
#define NC   (NH*NDK)     /* 2048 channels */
#define KS   (3*ND)       /* 6144: split-precision K (hi|lo|hi) */
#define WSTRIDE ((size_t)NC*KS)

// ------------------------------------------------------------------
// Scratch (device globals; no runtime allocation allowed)
// ------------------------------------------------------------------
__device__ __nv_bfloat16 g_xs[(size_t)NTOK*KS];   // split activations
__device__ __nv_bfloat16 g_ws[6*WSTRIDE];         // 6 split weights (q,k,v,a,g,o)
__device__ float g_q0[NTOK*NC];
__device__ float g_k0[NTOK*NC];
__device__ float g_v0[NTOK*NC];
__device__ float g_qc[NTOK*NC];
__device__ float g_kc[NTOK*NC];
__device__ float g_vc[NTOK*NC];
__device__ float g_a [NTOK*NC];
__device__ float g_gt[NTOK*NC];
__device__ float g_o4[(size_t)NTOK*NC*4];         // 4 partial recurrence outputs / channel
__device__ float g_bt[NTOK*NH];

// ==================================================================
// Helpers
// ==================================================================
__device__ __forceinline__ uint32_t smem_u32(const void* p) {
    uint32_t r;
    asm("{ .reg .u64 t; cvta.to.shared.u64 t, %1; cvt.u32.u64 %0, t; }"
        : "=r"(r) : "l"(p));
    return r;
}
__device__ __forceinline__ void cp16(uint32_t dst, const void* src) {
    asm volatile("cp.async.cg.shared.global [%0], [%1], 16;\n" :: "r"(dst), "l"(src));
}
__device__ __forceinline__ void cp_commit() {
    asm volatile("cp.async.commit_group;\n" ::: "memory");
}
__device__ __forceinline__ void cp_wait1() {
    asm volatile("cp.async.wait_group 1;\n" ::: "memory");
}
__device__ __forceinline__ void cp_wait0() {
    asm volatile("cp.async.wait_group 0;\n" ::: "memory");
}
__device__ __forceinline__ void ldsm4(uint32_t& r0, uint32_t& r1, uint32_t& r2,
                                      uint32_t& r3, uint32_t addr) {
    asm volatile("ldmatrix.sync.aligned.m8n8.x4.shared.b16 {%0,%1,%2,%3}, [%4];"
                 : "=r"(r0), "=r"(r1), "=r"(r2), "=r"(r3) : "r"(addr));
}
__device__ __forceinline__ void mma16816(float* d, const uint32_t* a,
                                         uint32_t b0, uint32_t b1) {
    asm volatile(
        "mma.sync.aligned.m16n8k16.row.col.f32.bf16.bf16.f32 "
        "{%0,%1,%2,%3}, {%4,%5,%6,%7}, {%8,%9}, {%0,%1,%2,%3};"
        : "+f"(d[0]), "+f"(d[1]), "+f"(d[2]), "+f"(d[3])
        : "r"(a[0]), "r"(a[1]), "r"(a[2]), "r"(a[3]), "r"(b0), "r"(b1));
}
__device__ __forceinline__ float fsig(float z) {
    return 1.f / (1.f + __expf(-z));
}

// ---- packed f32x2 (sm_100-family base feature) ----
typedef unsigned long long u64;
__device__ __forceinline__ u64 pack2(float lo, float hi) {
    u64 r; asm("mov.b64 %0, {%1, %2};" : "=l"(r) : "f"(lo), "f"(hi)); return r;
}
__device__ __forceinline__ void unpack2(u64 v, float& lo, float& hi) {
    asm("mov.b64 {%0, %1}, %2;" : "=f"(lo), "=f"(hi) : "l"(v));
}
__device__ __forceinline__ u64 fma2(u64 a, u64 b, u64 c) {
    u64 d; asm("fma.rn.f32x2 %0, %1, %2, %3;" : "=l"(d) : "l"(a), "l"(b), "l"(c));
    return d;
}
__device__ __forceinline__ u64 mul2(u64 a, u64 b) {
    u64 d; asm("mul.rn.f32x2 %0, %1, %2;" : "=l"(d) : "l"(a), "l"(b));
    return d;
}
__device__ __forceinline__ u64 add2(u64 a, u64 b) {
    u64 d; asm("add.rn.f32x2 %0, %1, %2;" : "=l"(d) : "l"(a), "l"(b));
    return d;
}

// ==================================================================
// Tensor-core GEMM (HMMA): fused 5-projection (grid.x=80) or Wo (grid.x=16)
// 128x128 tile, BK=64, 3-stage cp.async pipeline (96 KB smem), 8 warps.
// (R5 configuration — verbatim; known-good local optimum.)
// ==================================================================
#define BK      64
#define KITERS  (KS/BK)      /* 96 */
#define STG_B   32768
#define STAGES  3
#define TG_SMEM (STAGES*STG_B)

__global__ void __launch_bounds__(256, 2)
tgemm(const __nv_bfloat16* __restrict__ A, const __nv_bfloat16* __restrict__ Bw,
      const float* __restrict__ bias_a,
      float* __restrict__ Cq, float* __restrict__ Ck, float* __restrict__ Cv,
      float* __restrict__ Ca, float* __restrict__ Cg)
{
    extern __shared__ __align__(1024) char smem[];
    const uint32_t sb = smem_u32(smem);

    const int tid  = threadIdx.x;
    const int lane = tid & 31;
    const int wid  = tid >> 5;
    const int wm   = wid & 3;
    const int wn   = wid >> 2;
    const int m0   = blockIdx.y * 128;
    const int n0g  = blockIdx.x * 128;
    const int seg  = blockIdx.x >> 4;
    const int col0 = (blockIdx.x & 15) * 128;

    const int r0 = tid >> 3;
    const int c0 = tid & 7;
    const uint32_t stOff = (uint32_t)(((c0 ^ (r0 & 7)) << 4));

    const __nv_bfloat16* gA = A  + (size_t)(m0  + r0) * KS + c0 * 8;
    const __nv_bfloat16* gB = Bw + (size_t)(n0g + r0) * KS + c0 * 8;

    const int la = lane & 15, ha = lane >> 4;
    const int arow = wm * 32 + la;
    const uint32_t aswz = arow & 7;
    const int brow = wn * 64 + (lane & 7) + ((lane >> 4) & 1) * 8;
    const uint32_t bswz = brow & 7;
    const uint32_t bsel = (lane >> 3) & 1;

    uint32_t aoff[4], boff[4];
#pragma unroll
    for (int kh = 0; kh < 4; kh++) {
        aoff[kh] = arow * 128 + (((uint32_t)((2 * kh + ha) ^ aswz)) << 4);
        boff[kh] = 16384 + brow * 128 + (((uint32_t)((2 * kh + bsel) ^ bswz)) << 4);
    }

    float acc[2][8][4];
#pragma unroll
    for (int mi = 0; mi < 2; mi++)
#pragma unroll
        for (int ni = 0; ni < 8; ni++)
#pragma unroll
            for (int e = 0; e < 4; e++) acc[mi][ni][e] = 0.f;

#pragma unroll
    for (int s = 0; s < STAGES - 1; s++) {
        const uint32_t base = sb + s * STG_B;
        const int kc = s * BK;
#pragma unroll
        for (int r = 0; r < 4; r++) {
            const uint32_t so = (r0 + 32 * r) * 128 + stOff;
            cp16(base + so,         gA + (size_t)(32 * r) * KS + kc);
            cp16(base + 16384 + so, gB + (size_t)(32 * r) * KS + kc);
        }
        cp_commit();
    }

    int stage = 0;
    for (int it = 0; it < KITERS; it++) {
        if (it < KITERS - 1) cp_wait1(); else cp_wait0();
        __syncthreads();

        if (it + 2 < KITERS) {
            const int ps = (stage + 2 >= STAGES) ? stage + 2 - STAGES : stage + 2;
            const uint32_t base = sb + ps * STG_B;
            const int kc = (it + 2) * BK;
#pragma unroll
            for (int r = 0; r < 4; r++) {
                const uint32_t so = (r0 + 32 * r) * 128 + stOff;
                cp16(base + so,         gA + (size_t)(32 * r) * KS + kc);
                cp16(base + 16384 + so, gB + (size_t)(32 * r) * KS + kc);
            }
        }
        cp_commit();

        const uint32_t base = sb + stage * STG_B;
        stage = (stage + 1 >= STAGES) ? 0 : stage + 1;

#pragma unroll
        for (int kh = 0; kh < 4; kh++) {
            uint32_t av[2][4];
            ldsm4(av[0][0], av[0][1], av[0][2], av[0][3], base + aoff[kh]);
            ldsm4(av[1][0], av[1][1], av[1][2], av[1][3], base + aoff[kh] + 2048);

            uint32_t bv[4][4];
#pragma unroll
            for (int p = 0; p < 4; p++)
                ldsm4(bv[p][0], bv[p][1], bv[p][2], bv[p][3],
                      base + boff[kh] + p * 2048);

#pragma unroll
            for (int mi = 0; mi < 2; mi++)
#pragma unroll
                for (int ni = 0; ni < 8; ni++) {
                    const int p = ni >> 1;
                    const int h = (ni & 1) * 2;
                    mma16816(acc[mi][ni], av[mi], bv[p][h], bv[p][h + 1]);
                }
        }
    }

    float* C = (seg == 0) ? Cq : (seg == 1) ? Ck : (seg == 2) ? Cv
             : (seg == 3) ? Ca : Cg;
    const int et = (seg == 3) ? 1 : (seg == 4) ? 2 : 0;

    const int g  = lane >> 2;
    const int tg = lane & 3;
#pragma unroll
    for (int mi = 0; mi < 2; mi++) {
        const int row = m0 + wm * 32 + mi * 16 + g;
#pragma unroll
        for (int ni = 0; ni < 8; ni++) {
            const int col = col0 + wn * 64 + ni * 8 + tg * 2;
            float v0 = acc[mi][ni][0], v1 = acc[mi][ni][1];
            float v2 = acc[mi][ni][2], v3 = acc[mi][ni][3];
            if (et == 1) {
                const float b0 = bias_a[col], b1 = bias_a[col + 1];
                v0 = fsig(v0 + b0); v1 = fsig(v1 + b1);
                v2 = fsig(v2 + b0); v3 = fsig(v3 + b1);
            } else if (et == 2) {
                v0 = fsig(v0); v1 = fsig(v1); v2 = fsig(v2); v3 = fsig(v3);
            }
            *(float2*)(C + (size_t)row * NC + col)       = make_float2(v0, v1);
            *(float2*)(C + (size_t)(row + 8) * NC + col) = make_float2(v2, v3);
        }
    }
}

// ------------------------------------------------------------------
// Split fp32 -> bf16 hi/lo, K-concatenated (float4 vectorized).
// ------------------------------------------------------------------
__device__ __forceinline__ void split_body(const float* __restrict__ in,
                                           __nv_bfloat16* __restrict__ out,
                                           int mode, int i)
{
    const int r  = i >> 9;
    const int k4 = (i << 2) & 2047;
    const float4 a = ((const float4*)in)[i];

    __nv_bfloat162 h01 = __floats2bfloat162_rn(a.x, a.y);
    __nv_bfloat162 h23 = __floats2bfloat162_rn(a.z, a.w);
    const float lx = a.x - __bfloat162float(__low2bfloat16(h01));
    const float ly = a.y - __bfloat162float(__high2bfloat16(h01));
    const float lz = a.z - __bfloat162float(__low2bfloat16(h23));
    const float lw = a.w - __bfloat162float(__high2bfloat16(h23));
    __nv_bfloat162 l01 = __floats2bfloat162_rn(lx, ly);
    __nv_bfloat162 l23 = __floats2bfloat162_rn(lz, lw);

    uint2 hp, lp;
    hp.x = *(const uint32_t*)&h01; hp.y = *(const uint32_t*)&h23;
    lp.x = *(const uint32_t*)&l01; lp.y = *(const uint32_t*)&l23;

    __nv_bfloat16* base = out + (size_t)r * KS + k4;
    *(uint2*)(base) = hp;
    if (mode == 0) { *(uint2*)(base + 2048) = lp; *(uint2*)(base + 4096) = hp; }
    else           { *(uint2*)(base + 2048) = hp; *(uint2*)(base + 4096) = lp; }
}

__global__ void __launch_bounds__(256)
split_all(const float* __restrict__ x,  const float* __restrict__ Wq,
          const float* __restrict__ Wk, const float* __restrict__ Wv,
          const float* __restrict__ Wa, const float* __restrict__ Wg,
          const float* __restrict__ Wo,
          __nv_bfloat16* __restrict__ xs, __nv_bfloat16* __restrict__ ws)
{
    const int i = blockIdx.x * 256 + threadIdx.x;
    if (i >= (NTOK * ND) / 4) return;
    const int which = blockIdx.y;
    if (which == 0)      split_body(x,  xs, 0, i);
    else if (which == 1) split_body(Wq, ws + 0 * WSTRIDE, 1, i);
    else if (which == 2) split_body(Wk, ws + 1 * WSTRIDE, 1, i);
    else if (which == 3) split_body(Wv, ws + 2 * WSTRIDE, 1, i);
    else if (which == 4) split_body(Wa, ws + 3 * WSTRIDE, 1, i);
    else if (which == 5) split_body(Wg, ws + 4 * WSTRIDE, 1, i);
    else                 split_body(Wo, ws + 5 * WSTRIDE, 1, i);
}

// ------------------------------------------------------------------
// beta = sigmoid(x @ Wb^T + bb)
// ------------------------------------------------------------------
__global__ void __launch_bounds__(256)
beta_k(const float* __restrict__ x, const float* __restrict__ Wb,
       const float* __restrict__ bb, float* __restrict__ out)
{
    __shared__ float xs[ND];
    const int row = blockIdx.x;
    for (int i = threadIdx.x; i < ND; i += 256) xs[i] = x[(size_t)row * ND + i];
    __syncthreads();
    const int w = threadIdx.x >> 5, lane = threadIdx.x & 31;
    for (int h = w; h < NH; h += 8) {
        const float* wr = Wb + (size_t)h * ND;
        float s = 0.f;
        for (int i = lane; i < ND; i += 32) s = fmaf(xs[i], wr[i], s);
#pragma unroll
        for (int o = 16; o > 0; o >>= 1) s += __shfl_xor_sync(0xffffffffu, s, o);
        if (lane == 0) out[(size_t)row * NH + h] = fsig(s + bb[h]);
    }
}

// ------------------------------------------------------------------
// Fused causal depthwise conv (K=4) + bias + silu + scale.
// 2 consecutive tokens per thread (5 row-loads -> 2 outputs).
// ------------------------------------------------------------------
__global__ void __launch_bounds__(256)
conv3(const float* __restrict__ q0, const float* __restrict__ k0,
      const float* __restrict__ v0,
      const float* __restrict__ wq, const float* __restrict__ wk,
      const float* __restrict__ wv,
      const float* __restrict__ bq, const float* __restrict__ bk,
      const float* __restrict__ bv,
      float* __restrict__ qc, float* __restrict__ kc, float* __restrict__ vc)
{
    const int i = blockIdx.x * 256 + threadIdx.x;
    if (i >= (NTOK / 2) * (NC / 4)) return;

    const float* in; const float* w; const float* bias; float* out; float scale;
    if (blockIdx.y == 0)      { in = q0; w = wq; bias = bq; out = qc; scale = 1.f; }
    else if (blockIdx.y == 1) { in = k0; w = wk; bias = bk; out = kc; scale = 0.08838834764831845f; }
    else                      { in = v0; w = wv; bias = bv; out = vc; scale = 1.f; }

    const int cg   = i & (NC / 4 - 1);
    const int pair = i >> 9;
    const int c    = cg * 4;
    const int t0   = (pair & (NT / 2 - 1)) * 2;
    const int b    = pair >> 9;

    const float4 w0 = ((const float4*)w)[c + 0];
    const float4 w1 = ((const float4*)w)[c + 1];
    const float4 w2 = ((const float4*)w)[c + 2];
    const float4 w3 = ((const float4*)w)[c + 3];
    const float4 bi = *(const float4*)(bias + c);

    const float* p = in + ((size_t)b * NT + t0) * NC + c;
    const float4 z = make_float4(0.f, 0.f, 0.f, 0.f);
    const float4 xm3 = (t0 >= 3) ? *(const float4*)(p - 3 * NC) : z;
    const float4 xm2 = (t0 >= 2) ? *(const float4*)(p - 2 * NC) : z;
    const float4 xm1 = (t0 >= 1) ? *(const float4*)(p - NC)     : z;
    const float4 x0  = *(const float4*)p;
    const float4 xp1 = *(const float4*)(p + NC);

    float4 a0 = bi;
    a0.x = fmaf(w0.x, xm3.x, a0.x); a0.y = fmaf(w1.x, xm3.y, a0.y);
    a0.z = fmaf(w2.x, xm3.z, a0.z); a0.w = fmaf(w3.x, xm3.w, a0.w);
    a0.x = fmaf(w0.y, xm2.x, a0.x); a0.y = fmaf(w1.y, xm2.y, a0.y);
    a0.z = fmaf(w2.y, xm2.z, a0.z); a0.w = fmaf(w3.y, xm2.w, a0.w);
    a0.x = fmaf(w0.z, xm1.x, a0.x); a0.y = fmaf(w1.z, xm1.y, a0.y);
    a0.z = fmaf(w2.z, xm1.z, a0.z); a0.w = fmaf(w3.z, xm1.w, a0.w);
    a0.x = fmaf(w0.w, x0.x,  a0.x); a0.y = fmaf(w1.w, x0.y,  a0.y);
    a0.z = fmaf(w2.w, x0.z,  a0.z); a0.w = fmaf(w3.w, x0.w,  a0.w);

    float4 a1 = bi;
    a1.x = fmaf(w0.x, xm2.x, a1.x); a1.y = fmaf(w1.x, xm2.y, a1.y);
    a1.z = fmaf(w2.x, xm2.z, a1.z); a1.w = fmaf(w3.x, xm2.w, a1.w);
    a1.x = fmaf(w0.y, xm1.x, a1.x); a1.y = fmaf(w1.y, xm1.y, a1.y);
    a1.z = fmaf(w2.y, xm1.z, a1.z); a1.w = fmaf(w3.y, xm1.w, a1.w);
    a1.x = fmaf(w0.z, x0.x,  a1.x); a1.y = fmaf(w1.z, x0.y,  a1.y);
    a1.z = fmaf(w2.z, x0.z,  a1.z); a1.w = fmaf(w3.z, x0.w,  a1.w);
    a1.x = fmaf(w0.w, xp1.x, a1.x); a1.y = fmaf(w1.w, xp1.y, a1.y);
    a1.z = fmaf(w2.w, xp1.z, a1.z); a1.w = fmaf(w3.w, xp1.w, a1.w);

    float4 r0o, r1o;
    r0o.x = a0.x * fsig(a0.x) * scale; r0o.y = a0.y * fsig(a0.y) * scale;
    r0o.z = a0.z * fsig(a0.z) * scale; r0o.w = a0.w * fsig(a0.w) * scale;
    r1o.x = a1.x * fsig(a1.x) * scale; r1o.y = a1.y * fsig(a1.y) * scale;
    r1o.z = a1.z * fsig(a1.z) * scale; r1o.w = a1.w * fsig(a1.w) * scale;

    float* po = out + ((size_t)b * NT + t0) * NC + c;
    *(float4*)po        = r0o;
    *(float4*)(po + NC) = r1o;
}

// ------------------------------------------------------------------
// Recurrence, v-split 4x, 8-buffer staging (prefetch distance 4),
// one __syncthreads per 2 steps, pipelined Sk, PACKED f32x2 math.
// Thread (vloc = tid>>2, kq = tid&3) owns S[vloc][kq*32 .. +31]
// stored as 16 packed f32x2 pairs.
// ------------------------------------------------------------------
__global__ void __launch_bounds__(128)
recur2(const float* __restrict__ qc, const float* __restrict__ kc,
       const float* __restrict__ vc, const float* __restrict__ ga,
       const float* __restrict__ gbeta, float* __restrict__ o4)
{
    const int bid  = blockIdx.x;
    const int b    = bid >> 6;
    const int h    = (bid >> 2) & 15;
    const int vblk = bid & 3;
    const int tid  = threadIdx.x;
    const int vloc = tid >> 2;
    const int kq   = tid & 3;

    __shared__ __align__(16) float sk[8][160];
    __shared__ __align__(16) float sq[8][160];

    u64 S2[16];
#pragma unroll
    for (int j = 0; j < 16; j++) S2[j] = 0ull;

    const int kchan = h * NDK + tid;
    const int vchan = h * NDK + vblk * 32 + vloc;
    const int sidx  = (tid >> 5) * 40 + (tid & 31);
    const size_t tok0 = (size_t)b * NT;

    // prologue: stage bufs 0..3; preload v/a/beta for t = 0..3
#pragma unroll
    for (int tt = 0; tt < 4; tt++) {
        sk[tt][sidx] = kc[(tok0 + tt) * NC + kchan];
        sq[tt][sidx] = qc[(tok0 + tt) * NC + kchan];
    }
    float v0c = vc[(tok0 + 0) * NC + vchan], a0c = ga[(tok0 + 0) * NC + vchan];
    float v1c = vc[(tok0 + 1) * NC + vchan], a1c = ga[(tok0 + 1) * NC + vchan];
    float v2c = vc[(tok0 + 2) * NC + vchan], a2c = ga[(tok0 + 2) * NC + vchan];
    float v3c = vc[(tok0 + 3) * NC + vchan], a3c = ga[(tok0 + 3) * NC + vchan];
    float be0 = gbeta[(tok0 + 0) * NH + h];
    float be1 = gbeta[(tok0 + 1) * NH + h];
    float be2 = gbeta[(tok0 + 2) * NH + h];
    float be3 = gbeta[(tok0 + 3) * NH + h];

    float Skr = 0.f;   // reduced S.k for the CURRENT step (S_init = 0)

    auto step = [&](int buf, int nbuf, float v_cur, float a_cur, float be_cur, int t) {
        const ulonglong2* kb = (const ulonglong2*)&sk[buf][kq * 40];
        const ulonglong2* qb = (const ulonglong2*)&sq[buf][kq * 40];
        const ulonglong2* kn = (const ulonglong2*)&sk[nbuf][kq * 40];

        const float negcoef = be_cur * (v_cur - Skr);     // -coef
        const u64 a2 = pack2(a_cur, a_cur);
        const u64 c2 = pack2(negcoef, negcoef);

        u64 oacc[4] = {0ull, 0ull, 0ull, 0ull};
        u64 sacc[4] = {0ull, 0ull, 0ull, 0ull};
#pragma unroll
        for (int j = 0; j < 8; j++) {
            const ulonglong2 kk = kb[j];
            const ulonglong2 qq = qb[j];
            const ulonglong2 nn = kn[j];
            S2[2*j]   = fma2(a2, S2[2*j],   mul2(c2, kk.x));
            oacc[(2*j)   & 3] = fma2(S2[2*j],   qq.x, oacc[(2*j)   & 3]);
            sacc[(2*j)   & 3] = fma2(S2[2*j],   nn.x, sacc[(2*j)   & 3]);
            S2[2*j+1] = fma2(a2, S2[2*j+1], mul2(c2, kk.y));
            oacc[(2*j+1) & 3] = fma2(S2[2*j+1], qq.y, oacc[(2*j+1) & 3]);
            sacc[(2*j+1) & 3] = fma2(S2[2*j+1], nn.y, sacc[(2*j+1) & 3]);
        }
        const u64 osum = add2(add2(oacc[0], oacc[1]), add2(oacc[2], oacc[3]));
        const u64 ssum = add2(add2(sacc[0], sacc[1]), add2(sacc[2], sacc[3]));
        float ol, oh, sl, sh;
        unpack2(osum, ol, oh);
        unpack2(ssum, sl, sh);
        float skn = sl + sh;
        skn += __shfl_xor_sync(0xffffffffu, skn, 1);
        skn += __shfl_xor_sync(0xffffffffu, skn, 2);

        o4[((tok0 + t) * NC + vchan) * 4 + kq] = ol + oh;
        Skr = skn;
    };

    for (int t = 0; t < NT; t += 2) {
        __syncthreads();   // bufs t..t+3 staged & visible; prior reads complete

        // prefetch t+4, t+5 (regs)
        float k4 = 0.f, q4 = 0.f, v4 = 0.f, a4 = 0.f, be4 = 0.f;
        float k5 = 0.f, q5 = 0.f, v5 = 0.f, a5 = 0.f, be5 = 0.f;
        const bool more = (t + 4 < NT);
        if (more) {
            const size_t i4 = (tok0 + t + 4) * NC;
            const size_t i5 = (tok0 + t + 5) * NC;
            k4 = kc[i4 + kchan]; q4 = qc[i4 + kchan];
            v4 = vc[i4 + vchan]; a4 = ga[i4 + vchan];
            be4 = gbeta[(tok0 + t + 4) * NH + h];
            k5 = kc[i5 + kchan]; q5 = qc[i5 + kchan];
            v5 = vc[i5 + vchan]; a5 = ga[i5 + vchan];
            be5 = gbeta[(tok0 + t + 5) * NH + h];
        }

        step(t & 7,       (t + 1) & 7, v0c, a0c, be0, t);
        step((t + 1) & 7, (t + 2) & 7, v1c, a1c, be1, t + 1);

        if (more) {
            sk[(t + 4) & 7][sidx] = k4; sq[(t + 4) & 7][sidx] = q4;
            sk[(t + 5) & 7][sidx] = k5; sq[(t + 5) & 7][sidx] = q5;
        }
        v0c = v2c; a0c = a2c; be0 = be2;
        v1c = v3c; a1c = a3c; be1 = be3;
        v2c = v4;  a2c = a4;  be2 = be4;
        v3c = v5;  a3c = a5;  be3 = be5;
    }
}

// ------------------------------------------------------------------
// Sum 4 partials + LayerNorm + gate + bf16 split directly into g_xs.
// ------------------------------------------------------------------
__global__ void __launch_bounds__(128)
ln_gate_split(const float* __restrict__ o4, const float* __restrict__ gg,
              const float* __restrict__ ln_g, const float* __restrict__ ln_b,
              __nv_bfloat16* __restrict__ xs)
{
    const int bid = blockIdx.x;
    const int tok = bid >> 4, h = bid & 15;
    const int v = threadIdx.x, lane = v & 31, wid = v >> 5;
    const int chan = h * NDK + v;
    const size_t idx = (size_t)tok * NC + chan;

    const float4 part = ((const float4*)o4)[idx];
    const float o = (part.x + part.y) + (part.z + part.w);

    __shared__ float red[8];
    float rs = o, rs2 = o * o;
#pragma unroll
    for (int off = 16; off > 0; off >>= 1) {
        rs  += __shfl_xor_sync(0xffffffffu, rs,  off);
        rs2 += __shfl_xor_sync(0xffffffffu, rs2, off);
    }
    if (lane == 0) { red[wid] = rs; red[4 + wid] = rs2; }
    __syncthreads();
    const float mu  = (red[0] + red[1] + red[2] + red[3]) * (1.f / 128.f);
    const float ms  = (red[4] + red[5] + red[6] + red[7]) * (1.f / 128.f);
    const float var = ms - mu * mu;
    const float y = ((o - mu) * rsqrtf(var + 1e-5f) * ln_g[v] + ln_b[v]) * gg[idx];

    const __nv_bfloat16 hbf = __float2bfloat16(y);
    const __nv_bfloat16 lbf = __float2bfloat16(y - __bfloat162float(hbf));
    __nv_bfloat16* base = xs + (size_t)tok * KS + chan;
    base[0]    = hbf;
    base[2048] = lbf;
    base[4096] = hbf;
}

// ------------------------------------------------------------------
// Launch
// ------------------------------------------------------------------
extern "C" void kernel_launch(void* const* d_in, const int* in_sizes, int n_in,
                              void* d_out, int out_size)
{
    const float* x        = (const float*)d_in[0];
    const float* Wq       = (const float*)d_in[1];
    const float* Wk       = (const float*)d_in[2];
    const float* Wv       = (const float*)d_in[3];
    const float* Wa       = (const float*)d_in[4];
    const float* ba       = (const float*)d_in[5];
    const float* Wb       = (const float*)d_in[6];
    const float* bb       = (const float*)d_in[7];
    const float* conv_q_w = (const float*)d_in[8];
    const float* conv_q_b = (const float*)d_in[9];
    const float* conv_k_w = (const float*)d_in[10];
    const float* conv_k_b = (const float*)d_in[11];
    const float* conv_v_w = (const float*)d_in[12];
    const float* conv_v_b = (const float*)d_in[13];
    const float* Wg       = (const float*)d_in[14];
    const float* ln_g     = (const float*)d_in[15];
    const float* ln_b     = (const float*)d_in[16];
    const float* Wo       = (const float*)d_in[17];
    float* out = (float*)d_out;

    __nv_bfloat16 *xs, *ws;
    float *q0, *k0, *v0, *qc, *kc, *vc, *pa, *pg, *po4, *pbeta;
    cudaGetSymbolAddress((void**)&xs,    g_xs);
    cudaGetSymbolAddress((void**)&ws,    g_ws);
    cudaGetSymbolAddress((void**)&q0,    g_q0);
    cudaGetSymbolAddress((void**)&k0,    g_k0);
    cudaGetSymbolAddress((void**)&v0,    g_v0);
    cudaGetSymbolAddress((void**)&qc,    g_qc);
    cudaGetSymbolAddress((void**)&kc,    g_kc);
    cudaGetSymbolAddress((void**)&vc,    g_vc);
    cudaGetSymbolAddress((void**)&pa,    g_a);
    cudaGetSymbolAddress((void**)&pg,    g_gt);
    cudaGetSymbolAddress((void**)&po4,   g_o4);
    cudaGetSymbolAddress((void**)&pbeta, g_bt);

    static bool attr_set = false;
    if (!attr_set) {
        cudaFuncSetAttribute(tgemm, cudaFuncAttributeMaxDynamicSharedMemorySize, TG_SMEM);
        attr_set = true;
    }

    const int q4blk = ((NTOK * ND) / 4 + 255) / 256;       // 4096
    const int c2blk = ((NTOK / 2) * (NC / 4) + 255) / 256; // 2048

    // all splits (x + 6 weights) in one launch; beta from fp32 x
    split_all<<<dim3(q4blk, 7), 256>>>(x, Wq, Wk, Wv, Wa, Wg, Wo, xs, ws);
    beta_k<<<NTOK, 256>>>(x, Wb, bb, pbeta);

    // fused 5-projection GEMM (q, k, v, a, g) — N = 10240
    tgemm<<<dim3(80, 16), 256, TG_SMEM>>>(xs, ws, ba, q0, k0, v0, pa, pg);

    // fused conv + silu (q, k*DK^-0.5, v), 2 tokens per thread
    conv3<<<dim3(c2blk, 3), 256>>>(q0, k0, v0, conv_q_w, conv_k_w, conv_v_w,
                                   conv_q_b, conv_k_b, conv_v_b, qc, kc, vc);

    // recurrence (v-split 4x, pipelined Sk, f32x2) then LN + gate + split into xs
    recur2<<<NB * NH * 4, 128>>>(qc, kc, vc, pa, pbeta, po4);
    ln_gate_split<<<NTOK * NH, 128>>>(po4, pg, ln_g, ln_b, xs);

    // output projection (seg = 0 -> plain store to out)
    tgemm<<<dim3(16, 16), 256, TG_SMEM>>>(xs, ws + 5 * WSTRIDE, nullptr,
                                          out, out, out, out, out);
}

// round 11
// speedup vs baseline: 1.2842x; 1.0215x over previous
#include <cuda_runtime.h>
#include <cuda_bf16.h>
#include <math.h>
#include <stdint.h>

#define NB   2
#define NT   1024
#define ND   2048
#define NH   16
#define NDK  128
#define NTOK (NB*NT)      /* 2048 tokens */
#define NC   (NH*NDK)     /* 2048 channels */
#define KS   (3*ND)       /* 6144: split-precision K (hi|lo|hi) */
#define WSTRIDE ((size_t)NC*KS)

// ------------------------------------------------------------------
// Scratch (device globals; no runtime allocation allowed)
// ------------------------------------------------------------------
__device__ __nv_bfloat16 g_xs[(size_t)NTOK*KS];   // split activations
__device__ __nv_bfloat16 g_ws[6*WSTRIDE];         // 6 split weights (q,k,v,a,g,o)
__device__ float g_q0[NTOK*NC];
__device__ float g_k0[NTOK*NC];
__device__ float g_v0[NTOK*NC];
__device__ float g_qc[NTOK*NC];
__device__ float g_kc[NTOK*NC];
__device__ float g_vc[NTOK*NC];
__device__ float g_a [NTOK*NC];
__device__ float g_gt[NTOK*NC];
__device__ float g_o1[NTOK*NC];                   // reduced recurrence output
__device__ float g_bt[NTOK*NH];

// ==================================================================
// Helpers
// ==================================================================
__device__ __forceinline__ uint32_t smem_u32(const void* p) {
    uint32_t r;
    asm("{ .reg .u64 t; cvta.to.shared.u64 t, %1; cvt.u32.u64 %0, t; }"
        : "=r"(r) : "l"(p));
    return r;
}
__device__ __forceinline__ void cp16(uint32_t dst, const void* src) {
    asm volatile("cp.async.cg.shared.global [%0], [%1], 16;\n" :: "r"(dst), "l"(src));
}
__device__ __forceinline__ void cp_commit() {
    asm volatile("cp.async.commit_group;\n" ::: "memory");
}
__device__ __forceinline__ void cp_wait1() {
    asm volatile("cp.async.wait_group 1;\n" ::: "memory");
}
__device__ __forceinline__ void cp_wait0() {
    asm volatile("cp.async.wait_group 0;\n" ::: "memory");
}
__device__ __forceinline__ void ldsm4(uint32_t& r0, uint32_t& r1, uint32_t& r2,
                                      uint32_t& r3, uint32_t addr) {
    asm volatile("ldmatrix.sync.aligned.m8n8.x4.shared.b16 {%0,%1,%2,%3}, [%4];"
                 : "=r"(r0), "=r"(r1), "=r"(r2), "=r"(r3) : "r"(addr));
}
__device__ __forceinline__ void mma16816(float* d, const uint32_t* a,
                                         uint32_t b0, uint32_t b1) {
    asm volatile(
        "mma.sync.aligned.m16n8k16.row.col.f32.bf16.bf16.f32 "
        "{%0,%1,%2,%3}, {%4,%5,%6,%7}, {%8,%9}, {%0,%1,%2,%3};"
        : "+f"(d[0]), "+f"(d[1]), "+f"(d[2]), "+f"(d[3])
        : "r"(a[0]), "r"(a[1]), "r"(a[2]), "r"(a[3]), "r"(b0), "r"(b1));
}
__device__ __forceinline__ float fsig(float z) {
    return 1.f / (1.f + __expf(-z));
}

// ---- packed f32x2 (sm_100-family base feature) ----
typedef unsigned long long u64;
__device__ __forceinline__ u64 pack2(float lo, float hi) {
    u64 r; asm("mov.b64 %0, {%1, %2};" : "=l"(r) : "f"(lo), "f"(hi)); return r;
}
__device__ __forceinline__ void unpack2(u64 v, float& lo, float& hi) {
    asm("mov.b64 {%0, %1}, %2;" : "=f"(lo), "=f"(hi) : "l"(v));
}
__device__ __forceinline__ u64 fma2(u64 a, u64 b, u64 c) {
    u64 d; asm("fma.rn.f32x2 %0, %1, %2, %3;" : "=l"(d) : "l"(a), "l"(b), "l"(c));
    return d;
}
__device__ __forceinline__ u64 mul2(u64 a, u64 b) {
    u64 d; asm("mul.rn.f32x2 %0, %1, %2;" : "=l"(d) : "l"(a), "l"(b));
    return d;
}
__device__ __forceinline__ u64 add2(u64 a, u64 b) {
    u64 d; asm("add.rn.f32x2 %0, %1, %2;" : "=l"(d) : "l"(a), "l"(b));
    return d;
}

// ==================================================================
// Tensor-core GEMM (HMMA): fused 5-projection (grid.x=80) or Wo (grid.x=16)
// 128x128 tile, BK=64, 3-stage cp.async pipeline (96 KB smem), 8 warps.
// (R5 configuration — verbatim; known-good local optimum.)
// ==================================================================
#define BK      64
#define KITERS  (KS/BK)      /* 96 */
#define STG_B   32768
#define STAGES  3
#define TG_SMEM (STAGES*STG_B)

__global__ void __launch_bounds__(256, 2)
tgemm(const __nv_bfloat16* __restrict__ A, const __nv_bfloat16* __restrict__ Bw,
      const float* __restrict__ bias_a,
      float* __restrict__ Cq, float* __restrict__ Ck, float* __restrict__ Cv,
      float* __restrict__ Ca, float* __restrict__ Cg)
{
    extern __shared__ __align__(1024) char smem[];
    const uint32_t sb = smem_u32(smem);

    const int tid  = threadIdx.x;
    const int lane = tid & 31;
    const int wid  = tid >> 5;
    const int wm   = wid & 3;
    const int wn   = wid >> 2;
    const int m0   = blockIdx.y * 128;
    const int n0g  = blockIdx.x * 128;
    const int seg  = blockIdx.x >> 4;
    const int col0 = (blockIdx.x & 15) * 128;

    const int r0 = tid >> 3;
    const int c0 = tid & 7;
    const uint32_t stOff = (uint32_t)(((c0 ^ (r0 & 7)) << 4));

    const __nv_bfloat16* gA = A  + (size_t)(m0  + r0) * KS + c0 * 8;
    const __nv_bfloat16* gB = Bw + (size_t)(n0g + r0) * KS + c0 * 8;

    const int la = lane & 15, ha = lane >> 4;
    const int arow = wm * 32 + la;
    const uint32_t aswz = arow & 7;
    const int brow = wn * 64 + (lane & 7) + ((lane >> 4) & 1) * 8;
    const uint32_t bswz = brow & 7;
    const uint32_t bsel = (lane >> 3) & 1;

    uint32_t aoff[4], boff[4];
#pragma unroll
    for (int kh = 0; kh < 4; kh++) {
        aoff[kh] = arow * 128 + (((uint32_t)((2 * kh + ha) ^ aswz)) << 4);
        boff[kh] = 16384 + brow * 128 + (((uint32_t)((2 * kh + bsel) ^ bswz)) << 4);
    }

    float acc[2][8][4];
#pragma unroll
    for (int mi = 0; mi < 2; mi++)
#pragma unroll
        for (int ni = 0; ni < 8; ni++)
#pragma unroll
            for (int e = 0; e < 4; e++) acc[mi][ni][e] = 0.f;

#pragma unroll
    for (int s = 0; s < STAGES - 1; s++) {
        const uint32_t base = sb + s * STG_B;
        const int kc = s * BK;
#pragma unroll
        for (int r = 0; r < 4; r++) {
            const uint32_t so = (r0 + 32 * r) * 128 + stOff;
            cp16(base + so,         gA + (size_t)(32 * r) * KS + kc);
            cp16(base + 16384 + so, gB + (size_t)(32 * r) * KS + kc);
        }
        cp_commit();
    }

    int stage = 0;
    for (int it = 0; it < KITERS; it++) {
        if (it < KITERS - 1) cp_wait1(); else cp_wait0();
        __syncthreads();

        if (it + 2 < KITERS) {
            const int ps = (stage + 2 >= STAGES) ? stage + 2 - STAGES : stage + 2;
            const uint32_t base = sb + ps * STG_B;
            const int kc = (it + 2) * BK;
#pragma unroll
            for (int r = 0; r < 4; r++) {
                const uint32_t so = (r0 + 32 * r) * 128 + stOff;
                cp16(base + so,         gA + (size_t)(32 * r) * KS + kc);
                cp16(base + 16384 + so, gB + (size_t)(32 * r) * KS + kc);
            }
        }
        cp_commit();

        const uint32_t base = sb + stage * STG_B;
        stage = (stage + 1 >= STAGES) ? 0 : stage + 1;

#pragma unroll
        for (int kh = 0; kh < 4; kh++) {
            uint32_t av[2][4];
            ldsm4(av[0][0], av[0][1], av[0][2], av[0][3], base + aoff[kh]);
            ldsm4(av[1][0], av[1][1], av[1][2], av[1][3], base + aoff[kh] + 2048);

            uint32_t bv[4][4];
#pragma unroll
            for (int p = 0; p < 4; p++)
                ldsm4(bv[p][0], bv[p][1], bv[p][2], bv[p][3],
                      base + boff[kh] + p * 2048);

#pragma unroll
            for (int mi = 0; mi < 2; mi++)
#pragma unroll
                for (int ni = 0; ni < 8; ni++) {
                    const int p = ni >> 1;
                    const int h = (ni & 1) * 2;
                    mma16816(acc[mi][ni], av[mi], bv[p][h], bv[p][h + 1]);
                }
        }
    }

    float* C = (seg == 0) ? Cq : (seg == 1) ? Ck : (seg == 2) ? Cv
             : (seg == 3) ? Ca : Cg;
    const int et = (seg == 3) ? 1 : (seg == 4) ? 2 : 0;

    const int g  = lane >> 2;
    const int tg = lane & 3;
#pragma unroll
    for (int mi = 0; mi < 2; mi++) {
        const int row = m0 + wm * 32 + mi * 16 + g;
#pragma unroll
        for (int ni = 0; ni < 8; ni++) {
            const int col = col0 + wn * 64 + ni * 8 + tg * 2;
            float v0 = acc[mi][ni][0], v1 = acc[mi][ni][1];
            float v2 = acc[mi][ni][2], v3 = acc[mi][ni][3];
            if (et == 1) {
                const float b0 = bias_a[col], b1 = bias_a[col + 1];
                v0 = fsig(v0 + b0); v1 = fsig(v1 + b1);
                v2 = fsig(v2 + b0); v3 = fsig(v3 + b1);
            } else if (et == 2) {
                v0 = fsig(v0); v1 = fsig(v1); v2 = fsig(v2); v3 = fsig(v3);
            }
            *(float2*)(C + (size_t)row * NC + col)       = make_float2(v0, v1);
            *(float2*)(C + (size_t)(row + 8) * NC + col) = make_float2(v2, v3);
        }
    }
}

// ------------------------------------------------------------------
// Split fp32 -> bf16 hi/lo, K-concatenated (float4 vectorized).
// ------------------------------------------------------------------
__device__ __forceinline__ void split_body(const float* __restrict__ in,
                                           __nv_bfloat16* __restrict__ out,
                                           int mode, int i)
{
    const int r  = i >> 9;
    const int k4 = (i << 2) & 2047;
    const float4 a = ((const float4*)in)[i];

    __nv_bfloat162 h01 = __floats2bfloat162_rn(a.x, a.y);
    __nv_bfloat162 h23 = __floats2bfloat162_rn(a.z, a.w);
    const float lx = a.x - __bfloat162float(__low2bfloat16(h01));
    const float ly = a.y - __bfloat162float(__high2bfloat16(h01));
    const float lz = a.z - __bfloat162float(__low2bfloat16(h23));
    const float lw = a.w - __bfloat162float(__high2bfloat16(h23));
    __nv_bfloat162 l01 = __floats2bfloat162_rn(lx, ly);
    __nv_bfloat162 l23 = __floats2bfloat162_rn(lz, lw);

    uint2 hp, lp;
    hp.x = *(const uint32_t*)&h01; hp.y = *(const uint32_t*)&h23;
    lp.x = *(const uint32_t*)&l01; lp.y = *(const uint32_t*)&l23;

    __nv_bfloat16* base = out + (size_t)r * KS + k4;
    *(uint2*)(base) = hp;
    if (mode == 0) { *(uint2*)(base + 2048) = lp; *(uint2*)(base + 4096) = hp; }
    else           { *(uint2*)(base + 2048) = hp; *(uint2*)(base + 4096) = lp; }
}

__global__ void __launch_bounds__(256)
split_all(const float* __restrict__ x,  const float* __restrict__ Wq,
          const float* __restrict__ Wk, const float* __restrict__ Wv,
          const float* __restrict__ Wa, const float* __restrict__ Wg,
          const float* __restrict__ Wo,
          __nv_bfloat16* __restrict__ xs, __nv_bfloat16* __restrict__ ws)
{
    const int i = blockIdx.x * 256 + threadIdx.x;
    if (i >= (NTOK * ND) / 4) return;
    const int which = blockIdx.y;
    if (which == 0)      split_body(x,  xs, 0, i);
    else if (which == 1) split_body(Wq, ws + 0 * WSTRIDE, 1, i);
    else if (which == 2) split_body(Wk, ws + 1 * WSTRIDE, 1, i);
    else if (which == 3) split_body(Wv, ws + 2 * WSTRIDE, 1, i);
    else if (which == 4) split_body(Wa, ws + 3 * WSTRIDE, 1, i);
    else if (which == 5) split_body(Wg, ws + 4 * WSTRIDE, 1, i);
    else                 split_body(Wo, ws + 5 * WSTRIDE, 1, i);
}

// ------------------------------------------------------------------
// beta = sigmoid(x @ Wb^T + bb)
// ------------------------------------------------------------------
__global__ void __launch_bounds__(256)
beta_k(const float* __restrict__ x, const float* __restrict__ Wb,
       const float* __restrict__ bb, float* __restrict__ out)
{
    __shared__ float xs[ND];
    const int row = blockIdx.x;
    for (int i = threadIdx.x; i < ND; i += 256) xs[i] = x[(size_t)row * ND + i];
    __syncthreads();
    const int w = threadIdx.x >> 5, lane = threadIdx.x & 31;
    for (int h = w; h < NH; h += 8) {
        const float* wr = Wb + (size_t)h * ND;
        float s = 0.f;
        for (int i = lane; i < ND; i += 32) s = fmaf(xs[i], wr[i], s);
#pragma unroll
        for (int o = 16; o > 0; o >>= 1) s += __shfl_xor_sync(0xffffffffu, s, o);
        if (lane == 0) out[(size_t)row * NH + h] = fsig(s + bb[h]);
    }
}

// ------------------------------------------------------------------
// Fused causal depthwise conv (K=4) + bias + silu + scale.
// 4 consecutive tokens per thread (7 row-loads -> 4 outputs).
// ------------------------------------------------------------------
__global__ void __launch_bounds__(256)
conv3(const float* __restrict__ q0, const float* __restrict__ k0,
      const float* __restrict__ v0,
      const float* __restrict__ wq, const float* __restrict__ wk,
      const float* __restrict__ wv,
      const float* __restrict__ bq, const float* __restrict__ bk,
      const float* __restrict__ bv,
      float* __restrict__ qc, float* __restrict__ kc, float* __restrict__ vc)
{
    const int i = blockIdx.x * 256 + threadIdx.x;
    if (i >= (NTOK / 4) * (NC / 4)) return;

    const float* in; const float* w; const float* bias; float* out; float scale;
    if (blockIdx.y == 0)      { in = q0; w = wq; bias = bq; out = qc; scale = 1.f; }
    else if (blockIdx.y == 1) { in = k0; w = wk; bias = bk; out = kc; scale = 0.08838834764831845f; }
    else                      { in = v0; w = wv; bias = bv; out = vc; scale = 1.f; }

    const int cg   = i & (NC / 4 - 1);        // channel group
    const int quad = i >> 9;                   // token quad index
    const int c    = cg * 4;
    const int t0   = (quad & (NT / 4 - 1)) * 4;
    const int b    = quad >> 8;

    const float4 w0 = ((const float4*)w)[c + 0];
    const float4 w1 = ((const float4*)w)[c + 1];
    const float4 w2 = ((const float4*)w)[c + 2];
    const float4 w3 = ((const float4*)w)[c + 3];
    const float4 bi = *(const float4*)(bias + c);

    const float* p = in + ((size_t)b * NT + t0) * NC + c;
    const float4 z = make_float4(0.f, 0.f, 0.f, 0.f);
    float4 r[7];
    r[0] = (t0 >= 3) ? *(const float4*)(p - 3 * NC) : z;
    r[1] = (t0 >= 2) ? *(const float4*)(p - 2 * NC) : z;
    r[2] = (t0 >= 1) ? *(const float4*)(p - NC)     : z;
    r[3] = *(const float4*)p;
    r[4] = *(const float4*)(p + NC);
    r[5] = *(const float4*)(p + 2 * NC);
    r[6] = *(const float4*)(p + 3 * NC);

    float* po = out + ((size_t)b * NT + t0) * NC + c;
#pragma unroll
    for (int o = 0; o < 4; o++) {
        float4 acc = bi;
        acc.x = fmaf(w0.x, r[o].x,     acc.x); acc.y = fmaf(w1.x, r[o].y,     acc.y);
        acc.z = fmaf(w2.x, r[o].z,     acc.z); acc.w = fmaf(w3.x, r[o].w,     acc.w);
        acc.x = fmaf(w0.y, r[o + 1].x, acc.x); acc.y = fmaf(w1.y, r[o + 1].y, acc.y);
        acc.z = fmaf(w2.y, r[o + 1].z, acc.z); acc.w = fmaf(w3.y, r[o + 1].w, acc.w);
        acc.x = fmaf(w0.z, r[o + 2].x, acc.x); acc.y = fmaf(w1.z, r[o + 2].y, acc.y);
        acc.z = fmaf(w2.z, r[o + 2].z, acc.z); acc.w = fmaf(w3.z, r[o + 2].w, acc.w);
        acc.x = fmaf(w0.w, r[o + 3].x, acc.x); acc.y = fmaf(w1.w, r[o + 3].y, acc.y);
        acc.z = fmaf(w2.w, r[o + 3].z, acc.z); acc.w = fmaf(w3.w, r[o + 3].w, acc.w);

        float4 rr;
        rr.x = acc.x * fsig(acc.x) * scale;
        rr.y = acc.y * fsig(acc.y) * scale;
        rr.z = acc.z * fsig(acc.z) * scale;
        rr.w = acc.w * fsig(acc.w) * scale;
        *(float4*)(po + (size_t)o * NC) = rr;
    }
}

// ------------------------------------------------------------------
// Recurrence, v-split 4x, 8-buffer staging (prefetch distance 4),
// one __syncthreads per 2 steps, pipelined Sk, packed f32x2 math,
// in-kernel o-reduction over kq lanes (off the serial chain).
// ------------------------------------------------------------------
__global__ void __launch_bounds__(128)
recur2(const float* __restrict__ qc, const float* __restrict__ kc,
       const float* __restrict__ vc, const float* __restrict__ ga,
       const float* __restrict__ gbeta, float* __restrict__ o1)
{
    const int bid  = blockIdx.x;
    const int b    = bid >> 6;
    const int h    = (bid >> 2) & 15;
    const int vblk = bid & 3;
    const int tid  = threadIdx.x;
    const int vloc = tid >> 2;
    const int kq   = tid & 3;

    __shared__ __align__(16) float sk[8][160];
    __shared__ __align__(16) float sq[8][160];

    u64 S2[16];
#pragma unroll
    for (int j = 0; j < 16; j++) S2[j] = 0ull;

    const int kchan = h * NDK + tid;
    const int vchan = h * NDK + vblk * 32 + vloc;
    const int sidx  = (tid >> 5) * 40 + (tid & 31);
    const size_t tok0 = (size_t)b * NT;

    // prologue: stage bufs 0..3; preload v/a/beta for t = 0..3
#pragma unroll
    for (int tt = 0; tt < 4; tt++) {
        sk[tt][sidx] = kc[(tok0 + tt) * NC + kchan];
        sq[tt][sidx] = qc[(tok0 + tt) * NC + kchan];
    }
    float v0c = vc[(tok0 + 0) * NC + vchan], a0c = ga[(tok0 + 0) * NC + vchan];
    float v1c = vc[(tok0 + 1) * NC + vchan], a1c = ga[(tok0 + 1) * NC + vchan];
    float v2c = vc[(tok0 + 2) * NC + vchan], a2c = ga[(tok0 + 2) * NC + vchan];
    float v3c = vc[(tok0 + 3) * NC + vchan], a3c = ga[(tok0 + 3) * NC + vchan];
    float be0 = gbeta[(tok0 + 0) * NH + h];
    float be1 = gbeta[(tok0 + 1) * NH + h];
    float be2 = gbeta[(tok0 + 2) * NH + h];
    float be3 = gbeta[(tok0 + 3) * NH + h];

    float Skr = 0.f;   // reduced S.k for the CURRENT step (S_init = 0)

    auto step = [&](int buf, int nbuf, float v_cur, float a_cur, float be_cur, int t) {
        const ulonglong2* kb = (const ulonglong2*)&sk[buf][kq * 40];
        const ulonglong2* qb = (const ulonglong2*)&sq[buf][kq * 40];
        const ulonglong2* kn = (const ulonglong2*)&sk[nbuf][kq * 40];

        const float negcoef = be_cur * (v_cur - Skr);     // -coef
        const u64 a2 = pack2(a_cur, a_cur);
        const u64 c2 = pack2(negcoef, negcoef);

        u64 oacc[4] = {0ull, 0ull, 0ull, 0ull};
        u64 sacc[4] = {0ull, 0ull, 0ull, 0ull};
#pragma unroll
        for (int j = 0; j < 8; j++) {
            const ulonglong2 kk = kb[j];
            const ulonglong2 qq = qb[j];
            const ulonglong2 nn = kn[j];
            S2[2*j]   = fma2(a2, S2[2*j],   mul2(c2, kk.x));
            oacc[(2*j)   & 3] = fma2(S2[2*j],   qq.x, oacc[(2*j)   & 3]);
            sacc[(2*j)   & 3] = fma2(S2[2*j],   nn.x, sacc[(2*j)   & 3]);
            S2[2*j+1] = fma2(a2, S2[2*j+1], mul2(c2, kk.y));
            oacc[(2*j+1) & 3] = fma2(S2[2*j+1], qq.y, oacc[(2*j+1) & 3]);
            sacc[(2*j+1) & 3] = fma2(S2[2*j+1], nn.y, sacc[(2*j+1) & 3]);
        }
        const u64 osum = add2(add2(oacc[0], oacc[1]), add2(oacc[2], oacc[3]));
        const u64 ssum = add2(add2(sacc[0], sacc[1]), add2(sacc[2], sacc[3]));
        float ol, oh, sl, sh;
        unpack2(osum, ol, oh);
        unpack2(ssum, sl, sh);
        float skn = sl + sh;
        skn += __shfl_xor_sync(0xffffffffu, skn, 1);
        skn += __shfl_xor_sync(0xffffffffu, skn, 2);

        // o-reduction over kq lanes: NOT on the serial chain (store-only use)
        float op = ol + oh;
        op += __shfl_xor_sync(0xffffffffu, op, 1);
        op += __shfl_xor_sync(0xffffffffu, op, 2);
        if (kq == 0) o1[(tok0 + t) * NC + vchan] = op;

        Skr = skn;
    };

    for (int t = 0; t < NT; t += 2) {
        __syncthreads();   // bufs t..t+3 staged & visible; prior reads complete

        // prefetch t+4, t+5 (regs)
        float k4 = 0.f, q4 = 0.f, v4 = 0.f, a4 = 0.f, be4 = 0.f;
        float k5 = 0.f, q5 = 0.f, v5 = 0.f, a5 = 0.f, be5 = 0.f;
        const bool more = (t + 4 < NT);
        if (more) {
            const size_t i4 = (tok0 + t + 4) * NC;
            const size_t i5 = (tok0 + t + 5) * NC;
            k4 = kc[i4 + kchan]; q4 = qc[i4 + kchan];
            v4 = vc[i4 + vchan]; a4 = ga[i4 + vchan];
            be4 = gbeta[(tok0 + t + 4) * NH + h];
            k5 = kc[i5 + kchan]; q5 = qc[i5 + kchan];
            v5 = vc[i5 + vchan]; a5 = ga[i5 + vchan];
            be5 = gbeta[(tok0 + t + 5) * NH + h];
        }

        step(t & 7,       (t + 1) & 7, v0c, a0c, be0, t);
        step((t + 1) & 7, (t + 2) & 7, v1c, a1c, be1, t + 1);

        if (more) {
            sk[(t + 4) & 7][sidx] = k4; sq[(t + 4) & 7][sidx] = q4;
            sk[(t + 5) & 7][sidx] = k5; sq[(t + 5) & 7][sidx] = q5;
        }
        v0c = v2c; a0c = a2c; be0 = be2;
        v1c = v3c; a1c = a3c; be1 = be3;
        v2c = v4;  a2c = a4;  be2 = be4;
        v3c = v5;  a3c = a5;  be3 = be5;
    }
}

// ------------------------------------------------------------------
// LayerNorm + gate + bf16 split directly into g_xs.
// ------------------------------------------------------------------
__global__ void __launch_bounds__(128)
ln_gate_split(const float* __restrict__ o1, const float* __restrict__ gg,
              const float* __restrict__ ln_g, const float* __restrict__ ln_b,
              __nv_bfloat16* __restrict__ xs)
{
    const int bid = blockIdx.x;
    const int tok = bid >> 4, h = bid & 15;
    const int v = threadIdx.x, lane = v & 31, wid = v >> 5;
    const int chan = h * NDK + v;
    const size_t idx = (size_t)tok * NC + chan;

    const float o = o1[idx];

    __shared__ float red[8];
    float rs = o, rs2 = o * o;
#pragma unroll
    for (int off = 16; off > 0; off >>= 1) {
        rs  += __shfl_xor_sync(0xffffffffu, rs,  off);
        rs2 += __shfl_xor_sync(0xffffffffu, rs2, off);
    }
    if (lane == 0) { red[wid] = rs; red[4 + wid] = rs2; }
    __syncthreads();
    const float mu  = (red[0] + red[1] + red[2] + red[3]) * (1.f / 128.f);
    const float ms  = (red[4] + red[5] + red[6] + red[7]) * (1.f / 128.f);
    const float var = ms - mu * mu;
    const float y = ((o - mu) * rsqrtf(var + 1e-5f) * ln_g[v] + ln_b[v]) * gg[idx];

    const __nv_bfloat16 hbf = __float2bfloat16(y);
    const __nv_bfloat16 lbf = __float2bfloat16(y - __bfloat162float(hbf));
    __nv_bfloat16* base = xs + (size_t)tok * KS + chan;
    base[0]    = hbf;
    base[2048] = lbf;
    base[4096] = hbf;
}

// ------------------------------------------------------------------
// Launch
// ------------------------------------------------------------------
extern "C" void kernel_launch(void* const* d_in, const int* in_sizes, int n_in,
                              void* d_out, int out_size)
{
    const float* x        = (const float*)d_in[0];
    const float* Wq       = (const float*)d_in[1];
    const float* Wk       = (const float*)d_in[2];
    const float* Wv       = (const float*)d_in[3];
    const float* Wa       = (const float*)d_in[4];
    const float* ba       = (const float*)d_in[5];
    const float* Wb       = (const float*)d_in[6];
    const float* bb       = (const float*)d_in[7];
    const float* conv_q_w = (const float*)d_in[8];
    const float* conv_q_b = (const float*)d_in[9];
    const float* conv_k_w = (const float*)d_in[10];
    const float* conv_k_b = (const float*)d_in[11];
    const float* conv_v_w = (const float*)d_in[12];
    const float* conv_v_b = (const float*)d_in[13];
    const float* Wg       = (const float*)d_in[14];
    const float* ln_g     = (const float*)d_in[15];
    const float* ln_b     = (const float*)d_in[16];
    const float* Wo       = (const float*)d_in[17];
    float* out = (float*)d_out;

    __nv_bfloat16 *xs, *ws;
    float *q0, *k0, *v0, *qc, *kc, *vc, *pa, *pg, *po1, *pbeta;
    cudaGetSymbolAddress((void**)&xs,    g_xs);
    cudaGetSymbolAddress((void**)&ws,    g_ws);
    cudaGetSymbolAddress((void**)&q0,    g_q0);
    cudaGetSymbolAddress((void**)&k0,    g_k0);
    cudaGetSymbolAddress((void**)&v0,    g_v0);
    cudaGetSymbolAddress((void**)&qc,    g_qc);
    cudaGetSymbolAddress((void**)&kc,    g_kc);
    cudaGetSymbolAddress((void**)&vc,    g_vc);
    cudaGetSymbolAddress((void**)&pa,    g_a);
    cudaGetSymbolAddress((void**)&pg,    g_gt);
    cudaGetSymbolAddress((void**)&po1,   g_o1);
    cudaGetSymbolAddress((void**)&pbeta, g_bt);

    static bool attr_set = false;
    if (!attr_set) {
        cudaFuncSetAttribute(tgemm, cudaFuncAttributeMaxDynamicSharedMemorySize, TG_SMEM);
        attr_set = true;
    }

    const int q4blk = ((NTOK * ND) / 4 + 255) / 256;       // 4096
    const int c4blk = ((NTOK / 4) * (NC / 4) + 255) / 256; // 1024

    // all splits (x + 6 weights) in one launch; beta from fp32 x
    split_all<<<dim3(q4blk, 7), 256>>>(x, Wq, Wk, Wv, Wa, Wg, Wo, xs, ws);
    beta_k<<<NTOK, 256>>>(x, Wb, bb, pbeta);

    // fused 5-projection GEMM (q, k, v, a, g) — N = 10240
    tgemm<<<dim3(80, 16), 256, TG_SMEM>>>(xs, ws, ba, q0, k0, v0, pa, pg);

    // fused conv + silu (q, k*DK^-0.5, v), 4 tokens per thread
    conv3<<<dim3(c4blk, 3), 256>>>(q0, k0, v0, conv_q_w, conv_k_w, conv_v_w,
                                   conv_q_b, conv_k_b, conv_v_b, qc, kc, vc);

    // recurrence (v-split 4x, pipelined Sk, f32x2, in-kernel o-reduce)
    recur2<<<NB * NH * 4, 128>>>(qc, kc, vc, pa, pbeta, po1);
    ln_gate_split<<<NTOK * NH, 128>>>(po1, pg, ln_g, ln_b, xs);

    // output projection (seg = 0 -> plain store to out)
    tgemm<<<dim3(16, 16), 256, TG_SMEM>>>(xs, ws + 5 * WSTRIDE, nullptr,
                                          out, out, out, out, out);
}